// round 3
// baseline (speedup 1.0000x reference)
#include <cuda_runtime.h>
#include <math.h>

// Problem constants
#define NTH   512
#define VTH   1024
#define PAD   65
#define NV    16
#define ND    64
#define NH    256
#define NC    128
#define NTOK  8192
#define TT    64

typedef unsigned long long u64;

// Scratch (device globals: allocation-free rule)
__device__ float g_ctxp[32 * NH];
__device__ float g_varout[NTOK * NV * NH];

__device__ __forceinline__ float elu_f(float x)  { return x > 0.f ? x : (__expf(x) - 1.f); }
__device__ __forceinline__ float sigm_f(float x) { return 1.f / (1.f + __expf(-x)); }

// ---- packed fp32x2 helpers ----
__device__ __forceinline__ u64 pk2(float a, float b) {
    u64 r; asm("mov.b64 %0, {%1, %2};" : "=l"(r) : "f"(a), "f"(b)); return r;
}
__device__ __forceinline__ void fm2(u64& d, u64 a, u64 b) {
    asm("fma.rn.f32x2 %0, %1, %2, %0;" : "+l"(d) : "l"(a), "l"(b));
}
__device__ __forceinline__ float2 up2(u64 v) {
    float2 f; asm("mov.b64 {%0, %1}, %2;" : "=f"(f.x), "=f"(f.y) : "l"(v)); return f;
}

// 2-token x 4-colpair FMA group; needs wA, wB, xp0, xp1 in scope.
#define FMA8(A) do { \
    fm2(A[0][0], wA.x, xp0); fm2(A[0][1], wA.y, xp0); fm2(A[0][2], wB.x, xp0); fm2(A[0][3], wB.y, xp0); \
    fm2(A[1][0], wA.x, xp1); fm2(A[1][1], wA.y, xp1); fm2(A[1][2], wB.x, xp1); fm2(A[1][3], wB.y, xp1); \
} while (0)

#define ZERO24(A) do { \
    _Pragma("unroll") for (int _i = 0; _i < 2; ++_i) \
    _Pragma("unroll") for (int _j = 0; _j < 4; ++_j) A[_i][_j] = 0ull; \
} while (0)

// Double-buffered K-loop over a weight matrix with row stride WS (floats).
// XS(k) must expand to the smem row base for that k.
#define GEMM_LOOP(A, WPTR, WS, KN, XROW) do { \
    ulonglong2 wA = *(const ulonglong2*)(WPTR); \
    ulonglong2 wB = *(const ulonglong2*)((WPTR) + 4); \
    _Pragma("unroll 4") \
    for (int k = 0; k < (KN) - 1; ++k) { \
        ulonglong2 nA = *(const ulonglong2*)((WPTR) + (size_t)(k + 1) * (WS)); \
        ulonglong2 nB = *(const ulonglong2*)((WPTR) + (size_t)(k + 1) * (WS) + 4); \
        const float* _xr = (XROW) + k * PAD; \
        u64 xp0 = pk2(_xr[t0], _xr[t0]); \
        u64 xp1 = pk2(_xr[t0 + 1], _xr[t0 + 1]); \
        FMA8(A); \
        wA = nA; wB = nB; \
    } \
    { \
        const float* _xr = (XROW) + ((KN) - 1) * PAD; \
        u64 xp0 = pk2(_xr[t0], _xr[t0]); \
        u64 xp1 = pk2(_xr[t0 + 1], _xr[t0 + 1]); \
        FMA8(A); \
    } \
} while (0)

// GSTEP for the 512-thread wg kernel (4 tok x 4 colpair)
#define GSTEP(ACC) do { \
    u64 _xp; \
    _xp = pk2(xs0, xs0); fm2(ACC[0][0], wA.x, _xp); fm2(ACC[0][1], wA.y, _xp); fm2(ACC[0][2], wB.x, _xp); fm2(ACC[0][3], wB.y, _xp); \
    _xp = pk2(xs1, xs1); fm2(ACC[1][0], wA.x, _xp); fm2(ACC[1][1], wA.y, _xp); fm2(ACC[1][2], wB.x, _xp); fm2(ACC[1][3], wB.y, _xp); \
    _xp = pk2(xs2, xs2); fm2(ACC[2][0], wA.x, _xp); fm2(ACC[2][1], wA.y, _xp); fm2(ACC[2][2], wB.x, _xp); fm2(ACC[2][3], wB.y, _xp); \
    _xp = pk2(xs3, xs3); fm2(ACC[3][0], wA.x, _xp); fm2(ACC[3][1], wA.y, _xp); fm2(ACC[3][2], wB.x, _xp); fm2(ACC[3][3], wB.y, _xp); \
} while (0)

#define ZERO44(ACC) do { \
    _Pragma("unroll") for (int _i = 0; _i < 4; ++_i) \
    _Pragma("unroll") for (int _j = 0; _j < 4; ++_j) ACC[_i][_j] = 0ull; \
} while (0)

// ---------------------------------------------------------------------------
// Kernel 0: context projection
// ---------------------------------------------------------------------------
__global__ void ctx_kernel(const float* __restrict__ ctx, const float* __restrict__ wctx)
{
    int b = blockIdx.x;
    int h = threadIdx.x;
    float acc = 0.f;
    for (int c = 0; c < NC; ++c)
        acc += ctx[b * NC + c] * wctx[c * NH + h];
    g_ctxp[b * NH + h] = acc;
}

// ---------------------------------------------------------------------------
// Kernel 1: weight GRN -> softmax weights (unchanged from R2)
// ---------------------------------------------------------------------------
__global__ __launch_bounds__(NTH, 1)
void wg_kernel(const float* __restrict__ x,
               const float* __restrict__ fc1w, const float* __restrict__ fc1b,
               const float* __restrict__ fc2w, const float* __restrict__ fc2b,
               const float* __restrict__ gluw, const float* __restrict__ glub,
               const float* __restrict__ skw,  const float* __restrict__ skb,
               const float* __restrict__ lng,  const float* __restrict__ lnb,
               float* __restrict__ outw)
{
    extern __shared__ float sm[];
    float* sx  = sm;                       // [128][PAD]
    float* ash = sx  + 128 * PAD;          // [256][PAD]
    float* bsh = ash + 256 * PAD;          // [256][PAD]
    float* rsh = bsh + 256 * PAD;          // [64][16]
    float* gsh = rsh + 64 * 16;            // [64][32]

    const int tid  = threadIdx.x;
    const int warp = tid >> 5, lane = tid & 31;
    const int t0 = warp * 4;
    const int c0 = lane * 8;
    const int n0 = blockIdx.x * TT;
    const int tR = tid >> 3, jR = tid & 7;

    u64 acc[4][4];
    ZERO44(acc);
    float r0 = 0.f, r1 = 0.f;

    for (int kt = 0; kt < 8; ++kt) {
        for (int i = tid; i < TT * 128; i += NTH) {
            int t = i >> 7, k = i & 127;
            sx[k * PAD + t] = x[(size_t)(n0 + t) * 1024 + kt * 128 + k];
        }
        __syncthreads();
        const float* W = fc1w + (size_t)(kt * 128) * NH + c0;
#pragma unroll 2
        for (int k = 0; k < 128; ++k) {
            ulonglong2 wA = *(const ulonglong2*)(W + (size_t)k * NH);
            ulonglong2 wB = *(const ulonglong2*)(W + (size_t)k * NH + 4);
            float xs0 = sx[k * PAD + t0 + 0];
            float xs1 = sx[k * PAD + t0 + 1];
            float xs2 = sx[k * PAD + t0 + 2];
            float xs3 = sx[k * PAD + t0 + 3];
            GSTEP(acc);
        }
        const float* Ws = skw + (size_t)(kt * 128) * NV;
#pragma unroll 4
        for (int k = 0; k < 128; ++k) {
            float xv = sx[k * PAD + tR];
            r0 += xv * Ws[k * NV + jR];
            r1 += xv * Ws[k * NV + jR + 8];
        }
        __syncthreads();
    }

    {
        const int b = n0 >> 8;
#pragma unroll
        for (int j = 0; j < 4; ++j) {
            int ca = c0 + 2 * j, cb = ca + 1;
            float ba = fc1b[ca] + g_ctxp[b * NH + ca];
            float bb = fc1b[cb] + g_ctxp[b * NH + cb];
#pragma unroll
            for (int i = 0; i < 4; ++i) {
                float2 p = up2(acc[i][j]);
                ash[ca * PAD + t0 + i] = elu_f(p.x + ba);
                ash[cb * PAD + t0 + i] = elu_f(p.y + bb);
            }
        }
        rsh[tR * 16 + jR]     = r0 + skb[jR];
        rsh[tR * 16 + jR + 8] = r1 + skb[jR + 8];
    }
    __syncthreads();

    ZERO44(acc);
    {
        const float* W2 = fc2w + c0;
#pragma unroll 2
        for (int k = 0; k < NH; ++k) {
            ulonglong2 wA = *(const ulonglong2*)(W2 + (size_t)k * NH);
            ulonglong2 wB = *(const ulonglong2*)(W2 + (size_t)k * NH + 4);
            float xs0 = ash[k * PAD + t0 + 0];
            float xs1 = ash[k * PAD + t0 + 1];
            float xs2 = ash[k * PAD + t0 + 2];
            float xs3 = ash[k * PAD + t0 + 3];
            GSTEP(acc);
        }
#pragma unroll
        for (int j = 0; j < 4; ++j) {
            int ca = c0 + 2 * j, cb = ca + 1;
            float ba = fc2b[ca], bb = fc2b[cb];
#pragma unroll
            for (int i = 0; i < 4; ++i) {
                float2 p = up2(acc[i][j]);
                bsh[ca * PAD + t0 + i] = p.x + ba;
                bsh[cb * PAD + t0 + i] = p.y + bb;
            }
        }
    }
    __syncthreads();

    {
        float a3[4] = {0.f, 0.f, 0.f, 0.f};
#pragma unroll 4
        for (int k = 0; k < NH; ++k) {
            float w = gluw[k * 32 + lane];
            a3[0] += bsh[k * PAD + t0 + 0] * w;
            a3[1] += bsh[k * PAD + t0 + 1] * w;
            a3[2] += bsh[k * PAD + t0 + 2] * w;
            a3[3] += bsh[k * PAD + t0 + 3] * w;
        }
        float gb = glub[lane];
#pragma unroll
        for (int i = 0; i < 4; ++i)
            gsh[(t0 + i) * 32 + lane] = a3[i] + gb;
    }
    __syncthreads();

    if (tid < TT) {
        int t = tid;
        float h[NV];
        float mu = 0.f;
#pragma unroll
        for (int v = 0; v < NV; ++v) {
            float a  = gsh[t * 32 + v];
            float bb = gsh[t * 32 + 16 + v];
            h[v] = a * sigm_f(bb) + rsh[t * 16 + v];
            mu += h[v];
        }
        mu *= (1.f / 16.f);
        float var = 0.f;
#pragma unroll
        for (int v = 0; v < NV; ++v) { float d = h[v] - mu; var += d * d; }
        var *= (1.f / 16.f);
        float rstd = rsqrtf(var + 1e-5f);
        float y[NV], m = -1e30f;
#pragma unroll
        for (int v = 0; v < NV; ++v) {
            y[v] = (h[v] - mu) * rstd * lng[v] + lnb[v];
            m = fmaxf(m, y[v]);
        }
        float s = 0.f;
#pragma unroll
        for (int v = 0; v < NV; ++v) { y[v] = __expf(y[v] - m); s += y[v]; }
        float inv = 1.f / s;
#pragma unroll
        for (int v = 0; v < NV; ++v)
            outw[(n0 + t) * NV + v] = y[v] * inv;
    }
}

// ---------------------------------------------------------------------------
// Kernel 2: per-variable GRN. 1024 threads, 32 warps = 8 tok-groups x 4 col-groups.
// Thread tile: 2 tokens x 8 cols. Double-buffered weight loads.
// ---------------------------------------------------------------------------
__global__ __launch_bounds__(VTH, 1)
void vg_kernel(const float* __restrict__ x,
               const float* __restrict__ fc1w, const float* __restrict__ fc1b,
               const float* __restrict__ fc2w, const float* __restrict__ fc2b,
               const float* __restrict__ gluw, const float* __restrict__ glub,
               const float* __restrict__ skw,  const float* __restrict__ skb,
               const float* __restrict__ lng,  const float* __restrict__ lnb,
               const float* __restrict__ weights)
{
    extern __shared__ float sm[];
    float* sx  = sm;                       // [64][PAD]   x tile, [d][t]
    float* ash = sx  + 64 * PAD;           // [256][PAD]  h1 / glu-a temp / hv
    float* bsh = ash + 256 * PAD;          // [256][PAD]  h2
    float* rsh = bsh + 256 * PAD;          // [256][PAD]  residual

    const int v  = blockIdx.y;
    const int n0 = blockIdx.x * TT;
    const int tid  = threadIdx.x;
    const int warp = tid >> 5, lane = tid & 31;
    const int cl = lane & 7, tl = lane >> 3;      // 8 col-lanes x 4 tok-lanes
    const int cg = warp & 3, tg = warp >> 2;      // 4 col-groups x 8 tok-groups
    const int t0 = tg * 8 + tl * 2;               // 2 tokens per thread
    const int c0 = cg * 64 + cl * 8;              // 8 cols per thread

    for (int i = tid; i < TT * ND; i += VTH) {
        int t = i >> 6, d = i & 63;
        sx[d * PAD + t] = x[((size_t)(n0 + t) * NV + v) * ND + d];
    }
    __syncthreads();

    u64 acc[2][4];

    // ---- stage 1a: h1 = elu(x @ fc1 + b1) -> ash ----
    {
        ZERO24(acc);
        const float* W1 = fc1w + (size_t)v * ND * NH + c0;
        GEMM_LOOP(acc, W1, NH, ND, sx);
#pragma unroll
        for (int j = 0; j < 4; ++j) {
            int ca = c0 + 2 * j, cb = ca + 1;
            float ba = fc1b[v * NH + ca], bb = fc1b[v * NH + cb];
            float2 p0 = up2(acc[0][j]);
            float2 p1 = up2(acc[1][j]);
            ash[ca * PAD + t0]     = elu_f(p0.x + ba);
            ash[cb * PAD + t0]     = elu_f(p0.y + bb);
            ash[ca * PAD + t0 + 1] = elu_f(p1.x + ba);
            ash[cb * PAD + t0 + 1] = elu_f(p1.y + bb);
        }
    }

    // ---- stage 1b: residual = x @ skip + bs -> rsh ----
    {
        ZERO24(acc);
        const float* Ws = skw + (size_t)v * ND * NH + c0;
        GEMM_LOOP(acc, Ws, NH, ND, sx);
#pragma unroll
        for (int j = 0; j < 4; ++j) {
            int ca = c0 + 2 * j, cb = ca + 1;
            float ba = skb[v * NH + ca], bb = skb[v * NH + cb];
            float2 p0 = up2(acc[0][j]);
            float2 p1 = up2(acc[1][j]);
            rsh[ca * PAD + t0]     = p0.x + ba;
            rsh[cb * PAD + t0]     = p0.y + bb;
            rsh[ca * PAD + t0 + 1] = p1.x + ba;
            rsh[cb * PAD + t0 + 1] = p1.y + bb;
        }
    }
    __syncthreads();

    // ---- stage 2: h2 = h1 @ fc2 + b2 -> bsh ----
    {
        ZERO24(acc);
        const float* W2 = fc2w + (size_t)v * NH * NH + c0;
        GEMM_LOOP(acc, W2, NH, NH, ash);
#pragma unroll
        for (int j = 0; j < 4; ++j) {
            int ca = c0 + 2 * j, cb = ca + 1;
            float ba = fc2b[v * NH + ca], bb = fc2b[v * NH + cb];
            float2 p0 = up2(acc[0][j]);
            float2 p1 = up2(acc[1][j]);
            bsh[ca * PAD + t0]     = p0.x + ba;
            bsh[cb * PAD + t0]     = p0.y + bb;
            bsh[ca * PAD + t0 + 1] = p1.x + ba;
            bsh[cb * PAD + t0 + 1] = p1.y + bb;
        }
    }
    __syncthreads();   // ash (h1) now dead; reuse as glu-a temp

    // ---- stage 3 pass 1: a-half of GLU -> ash (with bias) ----
    {
        ZERO24(acc);
        const float* Wa = gluw + (size_t)v * NH * 512 + c0;
        GEMM_LOOP(acc, Wa, 512, NH, bsh);
#pragma unroll
        for (int j = 0; j < 4; ++j) {
            int ca = c0 + 2 * j, cb = ca + 1;
            float ba = glub[v * 512 + ca], bb = glub[v * 512 + cb];
            float2 p0 = up2(acc[0][j]);
            float2 p1 = up2(acc[1][j]);
            ash[ca * PAD + t0]     = p0.x + ba;
            ash[cb * PAD + t0]     = p0.y + bb;
            ash[ca * PAD + t0 + 1] = p1.x + ba;
            ash[cb * PAD + t0 + 1] = p1.y + bb;
        }
    }

    // ---- stage 3 pass 2: b-half, then hv = a*sigm(b) + residual -> ash ----
    {
        ZERO24(acc);
        const float* Wb = gluw + (size_t)v * NH * 512 + 256 + c0;
        GEMM_LOOP(acc, Wb, 512, NH, bsh);
#pragma unroll
        for (int j = 0; j < 4; ++j) {
            int ca = c0 + 2 * j, cb = ca + 1;
            float ba = glub[v * 512 + 256 + ca], bb = glub[v * 512 + 256 + cb];
            float2 p0 = up2(acc[0][j]);
            float2 p1 = up2(acc[1][j]);
            // own slots: read a, combine, overwrite with hv
            ash[ca * PAD + t0]     = ash[ca * PAD + t0]     * sigm_f(p0.x + ba) + rsh[ca * PAD + t0];
            ash[cb * PAD + t0]     = ash[cb * PAD + t0]     * sigm_f(p0.y + bb) + rsh[cb * PAD + t0];
            ash[ca * PAD + t0 + 1] = ash[ca * PAD + t0 + 1] * sigm_f(p1.x + ba) + rsh[ca * PAD + t0 + 1];
            ash[cb * PAD + t0 + 1] = ash[cb * PAD + t0 + 1] * sigm_f(p1.y + bb) + rsh[cb * PAD + t0 + 1];
        }
    }
    __syncthreads();

    // ---- stage 4: LayerNorm(256), scale by weight, write varout ----
    {
        int t = tid >> 4;      // 0..63
        int j = tid & 15;      // 16-lane groups
        float s = 0.f, s2 = 0.f;
        for (int c = j; c < NH; c += 16) {
            float u = ash[c * PAD + t];
            s += u; s2 += u * u;
        }
#pragma unroll
        for (int off = 8; off > 0; off >>= 1) {
            s  += __shfl_xor_sync(0xffffffffu, s,  off, 16);
            s2 += __shfl_xor_sync(0xffffffffu, s2, off, 16);
        }
        float mu   = s * (1.f / 256.f);
        float var  = s2 * (1.f / 256.f) - mu * mu;
        float rstd = rsqrtf(var + 1e-5f);
        float w = weights[(n0 + t) * NV + v];
        float* dst = g_varout + ((size_t)(n0 + t) * NV + v) * NH;
        const float* gv = lng + v * NH;
        const float* bv = lnb + v * NH;
        for (int c = j; c < NH; c += 16) {
            float u = ash[c * PAD + t];
            float o = (u - mu) * rstd * gv[c] + bv[c];
            dst[c] = o * w;
        }
    }
}

// ---------------------------------------------------------------------------
// Kernel 3: selected[n][c] = sum_v varout[n][v][c]
// ---------------------------------------------------------------------------
__global__ void combine_kernel(float* __restrict__ out_sel)
{
    int n = blockIdx.x;
    int c = threadIdx.x;
    const float* p = g_varout + (size_t)n * NV * NH + c;
    float s = 0.f;
#pragma unroll
    for (int v = 0; v < NV; ++v) s += p[v * NH];
    out_sel[(size_t)n * NH + c] = s;
}

// ---------------------------------------------------------------------------
extern "C" void kernel_launch(void* const* d_in, const int* in_sizes, int n_in,
                              void* d_out, int out_size)
{
    const float* x        = (const float*)d_in[0];
    const float* context  = (const float*)d_in[1];
    const float* vg_fc1_w = (const float*)d_in[2];
    const float* vg_fc1_b = (const float*)d_in[3];
    const float* vg_fc2_w = (const float*)d_in[4];
    const float* vg_fc2_b = (const float*)d_in[5];
    const float* vg_glu_w = (const float*)d_in[6];
    const float* vg_glu_b = (const float*)d_in[7];
    const float* vg_skip_w= (const float*)d_in[8];
    const float* vg_skip_b= (const float*)d_in[9];
    const float* vg_ln_g  = (const float*)d_in[10];
    const float* vg_ln_b  = (const float*)d_in[11];
    const float* wg_fc1_w = (const float*)d_in[12];
    const float* wg_fc1_b = (const float*)d_in[13];
    const float* wg_ctx_w = (const float*)d_in[14];
    const float* wg_fc2_w = (const float*)d_in[15];
    const float* wg_fc2_b = (const float*)d_in[16];
    const float* wg_glu_w = (const float*)d_in[17];
    const float* wg_glu_b = (const float*)d_in[18];
    const float* wg_skip_w= (const float*)d_in[19];
    const float* wg_skip_b= (const float*)d_in[20];
    const float* wg_ln_g  = (const float*)d_in[21];
    const float* wg_ln_b  = (const float*)d_in[22];

    float* out      = (float*)d_out;
    float* out_sel  = out;
    float* out_wts  = out + (size_t)NTOK * NH;

    const int WG_SMEM = (128 * PAD + 2 * 256 * PAD + 64 * 16 + 64 * 32) * 4;
    const int VG_SMEM = (64 * PAD + 3 * 256 * PAD) * 4;
    cudaFuncSetAttribute(wg_kernel, cudaFuncAttributeMaxDynamicSharedMemorySize, WG_SMEM);
    cudaFuncSetAttribute(vg_kernel, cudaFuncAttributeMaxDynamicSharedMemorySize, VG_SMEM);

    ctx_kernel<<<32, NH>>>(context, wg_ctx_w);

    wg_kernel<<<NTOK / TT, NTH, WG_SMEM>>>(
        x, wg_fc1_w, wg_fc1_b, wg_fc2_w, wg_fc2_b,
        wg_glu_w, wg_glu_b, wg_skip_w, wg_skip_b, wg_ln_g, wg_ln_b, out_wts);

    vg_kernel<<<dim3(NTOK / TT, NV), VTH, VG_SMEM>>>(
        x, vg_fc1_w, vg_fc1_b, vg_fc2_w, vg_fc2_b,
        vg_glu_w, vg_glu_b, vg_skip_w, vg_skip_b, vg_ln_g, vg_ln_b, out_wts);

    combine_kernel<<<NTOK, NH>>>(out_sel);
}

// round 4
// speedup vs baseline: 1.4232x; 1.4232x over previous
#include <cuda_runtime.h>
#include <math.h>

// Problem constants
#define NTH   512
#define PAD   65
#define NV    16
#define ND    64
#define NH    256
#define NC    128
#define NTOK  8192
#define TT    64     // wg token tile
#define GT    128    // gemm token tile
#define SP    132    // glu smem pad (floats per row)

typedef unsigned long long u64;

// Scratch (device globals: allocation-free rule)
__device__ float g_ctxp[32 * NH];
__device__ float g_xT[NV * ND * NTOK];        //  33.5MB  x transposed [v][d][n]
__device__ float g_h1[NV * NH * NTOK];        // 134MB    elu(fc1) [v][c][n]
__device__ float g_res[NV * NH * NTOK];       // 134MB    skip residual
__device__ float g_h2[NV * NH * NTOK];        // 134MB    fc2 out
__device__ float g_varout[NTOK * NV * NH];    // 134MB    weighted LN outputs

__device__ __forceinline__ float elu_f(float x)  { return x > 0.f ? x : (__expf(x) - 1.f); }
__device__ __forceinline__ float sigm_f(float x) { return 1.f / (1.f + __expf(-x)); }
__device__ __forceinline__ float idf(float x)    { return x; }

// ---- packed fp32x2 helpers ----
__device__ __forceinline__ u64 pk2(float a, float b) {
    u64 r; asm("mov.b64 %0, {%1, %2};" : "=l"(r) : "f"(a), "f"(b)); return r;
}
__device__ __forceinline__ void fm2(u64& d, u64 a, u64 b) {
    asm("fma.rn.f32x2 %0, %1, %2, %0;" : "+l"(d) : "l"(a), "l"(b));
}
__device__ __forceinline__ float2 up2(u64 v) {
    float2 f; asm("mov.b64 {%0, %1}, %2;" : "=f"(f.x), "=f"(f.y) : "l"(v)); return f;
}

// ===========================================================================
// GEMM framework: block = 128 tokens x 256 cols, 512 threads,
// thread tile = 8 tokens x 8 cols (4 col-pairs packed in u64).
// acc[j][i]: j = col-pair (0..3), i = token (0..7).
// ===========================================================================
#define GIDX \
    const int tid  = threadIdx.x; \
    const int lane = tid & 31, warp = tid >> 5; \
    const int cl = lane & 7, tl = lane >> 3; \
    const int cw = warp & 3, tw = warp >> 2; \
    const int c0 = cw * 64 + cl * 8; \
    const int tloc = tw * 32 + tl * 8; \
    const int v  = blockIdx.y; \
    const int n0 = blockIdx.x * GT; \
    const int n  = n0 + tloc;

#define GZERO() do { \
    _Pragma("unroll") for (int _j = 0; _j < 4; ++_j) \
    _Pragma("unroll") for (int _i = 0; _i < 8; ++_i) acc[_j][_i] = 0ull; \
} while (0)

#define FMA32() do { \
    fm2(acc[0][0], wA.x, xp0); fm2(acc[1][0], wA.y, xp0); fm2(acc[2][0], wB.x, xp0); fm2(acc[3][0], wB.y, xp0); \
    fm2(acc[0][1], wA.x, xp1); fm2(acc[1][1], wA.y, xp1); fm2(acc[2][1], wB.x, xp1); fm2(acc[3][1], wB.y, xp1); \
    fm2(acc[0][2], wA.x, xp2); fm2(acc[1][2], wA.y, xp2); fm2(acc[2][2], wB.x, xp2); fm2(acc[3][2], wB.y, xp2); \
    fm2(acc[0][3], wA.x, xp3); fm2(acc[1][3], wA.y, xp3); fm2(acc[2][3], wB.x, xp3); fm2(acc[3][3], wB.y, xp3); \
    fm2(acc[0][4], wA.x, xp4); fm2(acc[1][4], wA.y, xp4); fm2(acc[2][4], wB.x, xp4); fm2(acc[3][4], wB.y, xp4); \
    fm2(acc[0][5], wA.x, xp5); fm2(acc[1][5], wA.y, xp5); fm2(acc[2][5], wB.x, xp5); fm2(acc[3][5], wB.y, xp5); \
    fm2(acc[0][6], wA.x, xp6); fm2(acc[1][6], wA.y, xp6); fm2(acc[2][6], wB.x, xp6); fm2(acc[3][6], wB.y, xp6); \
    fm2(acc[0][7], wA.x, xp7); fm2(acc[1][7], wA.y, xp7); fm2(acc[2][7], wB.x, xp7); fm2(acc[3][7], wB.y, xp7); \
} while (0)

// K-loop: weights prefetched 1 ahead; x loaded per-iter (L1-hit broadcast).
#define GLOOP(APTR, WPTR, WS, KN) do { \
    const float* _A = (APTR); \
    const float* _W = (WPTR); \
    ulonglong2 wA = *(const ulonglong2*)_W; \
    ulonglong2 wB = *(const ulonglong2*)(_W + 4); \
    _Pragma("unroll 2") \
    for (int k = 0; k < (KN); ++k) { \
        float4 xa = *(const float4*)(_A + (size_t)k * NTOK); \
        float4 xb = *(const float4*)(_A + (size_t)k * NTOK + 4); \
        ulonglong2 nwA, nwB; \
        if (k + 1 < (KN)) { \
            nwA = *(const ulonglong2*)(_W + (size_t)(k + 1) * (WS)); \
            nwB = *(const ulonglong2*)(_W + (size_t)(k + 1) * (WS) + 4); \
        } \
        u64 xp0 = pk2(xa.x, xa.x), xp1 = pk2(xa.y, xa.y); \
        u64 xp2 = pk2(xa.z, xa.z), xp3 = pk2(xa.w, xa.w); \
        u64 xp4 = pk2(xb.x, xb.x), xp5 = pk2(xb.y, xb.y); \
        u64 xp6 = pk2(xb.z, xb.z), xp7 = pk2(xb.w, xb.w); \
        FMA32(); \
        wA = nwA; wB = nwB; \
    } \
} while (0)

// Epilogue: bias + OP, store thread tile transposed into [c][n] layout.
#define EPI(OUTP, BIASP, OP) do { \
    _Pragma("unroll") \
    for (int j = 0; j < 4; ++j) { \
        int colA = c0 + 2 * j, colB = colA + 1; \
        float ba = (BIASP)[colA], bb = (BIASP)[colB]; \
        float ax[8], ay[8]; \
        _Pragma("unroll") \
        for (int i = 0; i < 8; ++i) { \
            float2 p = up2(acc[j][i]); \
            ax[i] = OP(p.x + ba); ay[i] = OP(p.y + bb); \
        } \
        float* dA = (OUTP) + (size_t)colA * NTOK + n; \
        float* dB = (OUTP) + (size_t)colB * NTOK + n; \
        *(float4*)dA       = make_float4(ax[0], ax[1], ax[2], ax[3]); \
        *(float4*)(dA + 4) = make_float4(ax[4], ax[5], ax[6], ax[7]); \
        *(float4*)dB       = make_float4(ay[0], ay[1], ay[2], ay[3]); \
        *(float4*)(dB + 4) = make_float4(ay[4], ay[5], ay[6], ay[7]); \
    } \
} while (0)

// ---------------------------------------------------------------------------
// Kernel 0: context projection
// ---------------------------------------------------------------------------
__global__ void ctx_kernel(const float* __restrict__ ctx, const float* __restrict__ wctx)
{
    int b = blockIdx.x;
    int h = threadIdx.x;
    float acc = 0.f;
    for (int c = 0; c < NC; ++c)
        acc += ctx[b * NC + c] * wctx[c * NH + h];
    g_ctxp[b * NH + h] = acc;
}

// ---------------------------------------------------------------------------
// Kernel: transpose x[n][v][d] -> g_xT[v][d][n]
// ---------------------------------------------------------------------------
__global__ void xt_kernel(const float* __restrict__ x)
{
    __shared__ float s[64 * SP];
    const int v  = blockIdx.y;
    const int n0 = blockIdx.x * GT;
    const int tid = threadIdx.x;

#pragma unroll
    for (int r = 0; r < 8; ++r) {
        int idx = tid + r * 256;          // over (token, dquad)
        int t  = idx >> 4;                // 0..127
        int dq = idx & 15;                // 0..15
        float4 val = *(const float4*)(x + (size_t)(n0 + t) * 1024 + v * 64 + dq * 4);
        s[(dq * 4 + 0) * SP + t] = val.x;
        s[(dq * 4 + 1) * SP + t] = val.y;
        s[(dq * 4 + 2) * SP + t] = val.z;
        s[(dq * 4 + 3) * SP + t] = val.w;
    }
    __syncthreads();
#pragma unroll
    for (int r = 0; r < 8; ++r) {
        int idx = tid + r * 256;          // over (d, tokenquad)
        int d  = idx >> 5;                // 0..63
        int tq = idx & 31;                // 0..31
        float4 o = *(const float4*)(s + d * SP + tq * 4);
        *(float4*)(g_xT + ((size_t)v * ND + d) * NTOK + n0 + tq * 4) = o;
    }
}

// ---------------------------------------------------------------------------
// Kernel 1: weight GRN -> softmax weights (unchanged from R2)
// ---------------------------------------------------------------------------
#define GSTEP(ACC) do { \
    u64 _xp; \
    _xp = pk2(xs0, xs0); fm2(ACC[0][0], wA.x, _xp); fm2(ACC[0][1], wA.y, _xp); fm2(ACC[0][2], wB.x, _xp); fm2(ACC[0][3], wB.y, _xp); \
    _xp = pk2(xs1, xs1); fm2(ACC[1][0], wA.x, _xp); fm2(ACC[1][1], wA.y, _xp); fm2(ACC[1][2], wB.x, _xp); fm2(ACC[1][3], wB.y, _xp); \
    _xp = pk2(xs2, xs2); fm2(ACC[2][0], wA.x, _xp); fm2(ACC[2][1], wA.y, _xp); fm2(ACC[2][2], wB.x, _xp); fm2(ACC[2][3], wB.y, _xp); \
    _xp = pk2(xs3, xs3); fm2(ACC[3][0], wA.x, _xp); fm2(ACC[3][1], wA.y, _xp); fm2(ACC[3][2], wB.x, _xp); fm2(ACC[3][3], wB.y, _xp); \
} while (0)

#define ZERO44(ACC) do { \
    _Pragma("unroll") for (int _i = 0; _i < 4; ++_i) \
    _Pragma("unroll") for (int _j = 0; _j < 4; ++_j) ACC[_i][_j] = 0ull; \
} while (0)

__global__ __launch_bounds__(NTH, 1)
void wg_kernel(const float* __restrict__ x,
               const float* __restrict__ fc1w, const float* __restrict__ fc1b,
               const float* __restrict__ fc2w, const float* __restrict__ fc2b,
               const float* __restrict__ gluw, const float* __restrict__ glub,
               const float* __restrict__ skw,  const float* __restrict__ skb,
               const float* __restrict__ lng,  const float* __restrict__ lnb,
               float* __restrict__ outw)
{
    extern __shared__ float sm[];
    float* sx  = sm;                       // [128][PAD]
    float* ash = sx  + 128 * PAD;          // [256][PAD]
    float* bsh = ash + 256 * PAD;          // [256][PAD]
    float* rsh = bsh + 256 * PAD;          // [64][16]
    float* gsh = rsh + 64 * 16;            // [64][32]

    const int tid  = threadIdx.x;
    const int warp = tid >> 5, lane = tid & 31;
    const int t0 = warp * 4;
    const int c0 = lane * 8;
    const int n0 = blockIdx.x * TT;
    const int tR = tid >> 3, jR = tid & 7;

    u64 acc[4][4];
    ZERO44(acc);
    float r0 = 0.f, r1 = 0.f;

    for (int kt = 0; kt < 8; ++kt) {
        for (int i = tid; i < TT * 128; i += NTH) {
            int t = i >> 7, k = i & 127;
            sx[k * PAD + t] = x[(size_t)(n0 + t) * 1024 + kt * 128 + k];
        }
        __syncthreads();
        const float* W = fc1w + (size_t)(kt * 128) * NH + c0;
#pragma unroll 2
        for (int k = 0; k < 128; ++k) {
            ulonglong2 wA = *(const ulonglong2*)(W + (size_t)k * NH);
            ulonglong2 wB = *(const ulonglong2*)(W + (size_t)k * NH + 4);
            float xs0 = sx[k * PAD + t0 + 0];
            float xs1 = sx[k * PAD + t0 + 1];
            float xs2 = sx[k * PAD + t0 + 2];
            float xs3 = sx[k * PAD + t0 + 3];
            GSTEP(acc);
        }
        const float* Ws = skw + (size_t)(kt * 128) * NV;
#pragma unroll 4
        for (int k = 0; k < 128; ++k) {
            float xv = sx[k * PAD + tR];
            r0 += xv * Ws[k * NV + jR];
            r1 += xv * Ws[k * NV + jR + 8];
        }
        __syncthreads();
    }

    {
        const int b = n0 >> 8;
#pragma unroll
        for (int j = 0; j < 4; ++j) {
            int ca = c0 + 2 * j, cb = ca + 1;
            float ba = fc1b[ca] + g_ctxp[b * NH + ca];
            float bb = fc1b[cb] + g_ctxp[b * NH + cb];
#pragma unroll
            for (int i = 0; i < 4; ++i) {
                float2 p = up2(acc[i][j]);
                ash[ca * PAD + t0 + i] = elu_f(p.x + ba);
                ash[cb * PAD + t0 + i] = elu_f(p.y + bb);
            }
        }
        rsh[tR * 16 + jR]     = r0 + skb[jR];
        rsh[tR * 16 + jR + 8] = r1 + skb[jR + 8];
    }
    __syncthreads();

    ZERO44(acc);
    {
        const float* W2 = fc2w + c0;
#pragma unroll 2
        for (int k = 0; k < NH; ++k) {
            ulonglong2 wA = *(const ulonglong2*)(W2 + (size_t)k * NH);
            ulonglong2 wB = *(const ulonglong2*)(W2 + (size_t)k * NH + 4);
            float xs0 = ash[k * PAD + t0 + 0];
            float xs1 = ash[k * PAD + t0 + 1];
            float xs2 = ash[k * PAD + t0 + 2];
            float xs3 = ash[k * PAD + t0 + 3];
            GSTEP(acc);
        }
#pragma unroll
        for (int j = 0; j < 4; ++j) {
            int ca = c0 + 2 * j, cb = ca + 1;
            float ba = fc2b[ca], bb = fc2b[cb];
#pragma unroll
            for (int i = 0; i < 4; ++i) {
                float2 p = up2(acc[i][j]);
                bsh[ca * PAD + t0 + i] = p.x + ba;
                bsh[cb * PAD + t0 + i] = p.y + bb;
            }
        }
    }
    __syncthreads();

    {
        float a3[4] = {0.f, 0.f, 0.f, 0.f};
#pragma unroll 4
        for (int k = 0; k < NH; ++k) {
            float w = gluw[k * 32 + lane];
            a3[0] += bsh[k * PAD + t0 + 0] * w;
            a3[1] += bsh[k * PAD + t0 + 1] * w;
            a3[2] += bsh[k * PAD + t0 + 2] * w;
            a3[3] += bsh[k * PAD + t0 + 3] * w;
        }
        float gb = glub[lane];
#pragma unroll
        for (int i = 0; i < 4; ++i)
            gsh[(t0 + i) * 32 + lane] = a3[i] + gb;
    }
    __syncthreads();

    if (tid < TT) {
        int t = tid;
        float h[NV];
        float mu = 0.f;
#pragma unroll
        for (int v = 0; v < NV; ++v) {
            float a  = gsh[t * 32 + v];
            float bb = gsh[t * 32 + 16 + v];
            h[v] = a * sigm_f(bb) + rsh[t * 16 + v];
            mu += h[v];
        }
        mu *= (1.f / 16.f);
        float var = 0.f;
#pragma unroll
        for (int v = 0; v < NV; ++v) { float d = h[v] - mu; var += d * d; }
        var *= (1.f / 16.f);
        float rstd = rsqrtf(var + 1e-5f);
        float y[NV], m = -1e30f;
#pragma unroll
        for (int v = 0; v < NV; ++v) {
            y[v] = (h[v] - mu) * rstd * lng[v] + lnb[v];
            m = fmaxf(m, y[v]);
        }
        float s = 0.f;
#pragma unroll
        for (int v = 0; v < NV; ++v) { y[v] = __expf(y[v] - m); s += y[v]; }
        float inv = 1.f / s;
#pragma unroll
        for (int v = 0; v < NV; ++v)
            outw[(n0 + t) * NV + v] = y[v] * inv;
    }
}

// ---------------------------------------------------------------------------
// Kernel 2a: h1 = elu(x @ fc1 + b1), res = x @ skip + bs   (K = 64)
// ---------------------------------------------------------------------------
__global__ __launch_bounds__(512, 1)
void fc1skip_kernel(const float* __restrict__ fc1w, const float* __restrict__ fc1b,
                    const float* __restrict__ skw,  const float* __restrict__ skb)
{
    GIDX;
    const float* A = g_xT + (size_t)v * ND * NTOK + n;
    u64 acc[4][8];

    GZERO();
    GLOOP(A, fc1w + (size_t)v * ND * NH + c0, NH, ND);
    EPI(g_h1 + (size_t)v * NH * NTOK, fc1b + v * NH, elu_f);

    GZERO();
    GLOOP(A, skw + (size_t)v * ND * NH + c0, NH, ND);
    EPI(g_res + (size_t)v * NH * NTOK, skb + v * NH, idf);
}

// ---------------------------------------------------------------------------
// Kernel 2b: h2 = h1 @ fc2 + b2   (K = 256)
// ---------------------------------------------------------------------------
__global__ __launch_bounds__(512, 1)
void fc2_kernel(const float* __restrict__ fc2w, const float* __restrict__ fc2b)
{
    GIDX;
    const float* A = g_h1 + (size_t)v * NH * NTOK + n;
    u64 acc[4][8];

    GZERO();
    GLOOP(A, fc2w + (size_t)v * NH * NH + c0, NH, NH);
    EPI(g_h2 + (size_t)v * NH * NTOK, fc2b + v * NH, idf);
}

// ---------------------------------------------------------------------------
// Kernel 2c: GLU + residual + LN + weight-scale -> g_varout   (2x K = 256)
// ---------------------------------------------------------------------------
__global__ __launch_bounds__(512, 1)
void glu_kernel(const float* __restrict__ gluw, const float* __restrict__ glub,
                const float* __restrict__ lng,  const float* __restrict__ lnb,
                const float* __restrict__ wts)
{
    extern __shared__ float s_a[];     // [256][SP]
    GIDX;
    const float* A = g_h2 + (size_t)v * NH * NTOK + n;
    u64 acc[4][8];

    // pass 1: a-half -> smem
    GZERO();
    GLOOP(A, gluw + (size_t)v * NH * 512 + c0, 512, NH);
#pragma unroll
    for (int j = 0; j < 4; ++j) {
        int colA = c0 + 2 * j, colB = colA + 1;
        float ba = glub[v * 512 + colA], bb = glub[v * 512 + colB];
#pragma unroll
        for (int i = 0; i < 8; ++i) {
            float2 p = up2(acc[j][i]);
            s_a[colA * SP + tloc + i] = p.x + ba;
            s_a[colB * SP + tloc + i] = p.y + bb;
        }
    }

    // pass 2: b-half -> hv = a * sigm(b) + res, overwrite smem
    GZERO();
    GLOOP(A, gluw + (size_t)v * NH * 512 + 256 + c0, 512, NH);
#pragma unroll
    for (int j = 0; j < 4; ++j) {
        int colA = c0 + 2 * j, colB = colA + 1;
        float ba = glub[v * 512 + 256 + colA], bb = glub[v * 512 + 256 + colB];
        const float* rA = g_res + ((size_t)v * NH + colA) * NTOK + n;
        const float* rB = g_res + ((size_t)v * NH + colB) * NTOK + n;
        float4 ra0 = *(const float4*)rA, ra1 = *(const float4*)(rA + 4);
        float4 rb0 = *(const float4*)rB, rb1 = *(const float4*)(rB + 4);
        float ra[8] = {ra0.x, ra0.y, ra0.z, ra0.w, ra1.x, ra1.y, ra1.z, ra1.w};
        float rb[8] = {rb0.x, rb0.y, rb0.z, rb0.w, rb1.x, rb1.y, rb1.z, rb1.w};
#pragma unroll
        for (int i = 0; i < 8; ++i) {
            float2 p = up2(acc[j][i]);
            float av = s_a[colA * SP + tloc + i];
            float bv = s_a[colB * SP + tloc + i];
            s_a[colA * SP + tloc + i] = av * sigm_f(p.x + ba) + ra[i];
            s_a[colB * SP + tloc + i] = bv * sigm_f(p.y + bb) + rb[i];
        }
    }
    __syncthreads();

    // LayerNorm(256) per token + weight scale -> g_varout
    {
        int t  = tid >> 2;   // 0..127 (block-local token)
        int jj = tid & 3;
        float s = 0.f, s2 = 0.f;
        for (int c = jj; c < NH; c += 4) {
            float u = s_a[c * SP + t];
            s += u; s2 += u * u;
        }
        s  += __shfl_xor_sync(0xffffffffu, s,  1, 4);
        s  += __shfl_xor_sync(0xffffffffu, s,  2, 4);
        s2 += __shfl_xor_sync(0xffffffffu, s2, 1, 4);
        s2 += __shfl_xor_sync(0xffffffffu, s2, 2, 4);
        float mu   = s * (1.f / 256.f);
        float var  = s2 * (1.f / 256.f) - mu * mu;
        float rstd = rsqrtf(var + 1e-5f);
        float w = wts[(n0 + t) * NV + v];
        float* dst = g_varout + ((size_t)(n0 + t) * NV + v) * NH;
        const float* gv = lng + v * NH;
        const float* bv = lnb + v * NH;
        for (int c = jj * 64; c < jj * 64 + 64; c += 4) {
            float4 o;
            o.x = ((s_a[(c + 0) * SP + t] - mu) * rstd * gv[c + 0] + bv[c + 0]) * w;
            o.y = ((s_a[(c + 1) * SP + t] - mu) * rstd * gv[c + 1] + bv[c + 1]) * w;
            o.z = ((s_a[(c + 2) * SP + t] - mu) * rstd * gv[c + 2] + bv[c + 2]) * w;
            o.w = ((s_a[(c + 3) * SP + t] - mu) * rstd * gv[c + 3] + bv[c + 3]) * w;
            *(float4*)(dst + c) = o;
        }
    }
}

// ---------------------------------------------------------------------------
// Kernel 3: selected[n][c] = sum_v varout[n][v][c]
// ---------------------------------------------------------------------------
__global__ void combine_kernel(float* __restrict__ out_sel)
{
    int n = blockIdx.x;
    int c = threadIdx.x;
    const float* p = g_varout + (size_t)n * NV * NH + c;
    float s = 0.f;
#pragma unroll
    for (int v = 0; v < NV; ++v) s += p[v * NH];
    out_sel[(size_t)n * NH + c] = s;
}

// ---------------------------------------------------------------------------
extern "C" void kernel_launch(void* const* d_in, const int* in_sizes, int n_in,
                              void* d_out, int out_size)
{
    const float* x        = (const float*)d_in[0];
    const float* context  = (const float*)d_in[1];
    const float* vg_fc1_w = (const float*)d_in[2];
    const float* vg_fc1_b = (const float*)d_in[3];
    const float* vg_fc2_w = (const float*)d_in[4];
    const float* vg_fc2_b = (const float*)d_in[5];
    const float* vg_glu_w = (const float*)d_in[6];
    const float* vg_glu_b = (const float*)d_in[7];
    const float* vg_skip_w= (const float*)d_in[8];
    const float* vg_skip_b= (const float*)d_in[9];
    const float* vg_ln_g  = (const float*)d_in[10];
    const float* vg_ln_b  = (const float*)d_in[11];
    const float* wg_fc1_w = (const float*)d_in[12];
    const float* wg_fc1_b = (const float*)d_in[13];
    const float* wg_ctx_w = (const float*)d_in[14];
    const float* wg_fc2_w = (const float*)d_in[15];
    const float* wg_fc2_b = (const float*)d_in[16];
    const float* wg_glu_w = (const float*)d_in[17];
    const float* wg_glu_b = (const float*)d_in[18];
    const float* wg_skip_w= (const float*)d_in[19];
    const float* wg_skip_b= (const float*)d_in[20];
    const float* wg_ln_g  = (const float*)d_in[21];
    const float* wg_ln_b  = (const float*)d_in[22];

    float* out      = (float*)d_out;
    float* out_sel  = out;
    float* out_wts  = out + (size_t)NTOK * NH;

    const int WG_SMEM  = (128 * PAD + 2 * 256 * PAD + 64 * 16 + 64 * 32) * 4;
    const int GLU_SMEM = 256 * SP * 4;
    cudaFuncSetAttribute(wg_kernel,  cudaFuncAttributeMaxDynamicSharedMemorySize, WG_SMEM);
    cudaFuncSetAttribute(glu_kernel, cudaFuncAttributeMaxDynamicSharedMemorySize, GLU_SMEM);

    const dim3 ggrid(NTOK / GT, NV);

    ctx_kernel<<<32, NH>>>(context, wg_ctx_w);
    xt_kernel<<<ggrid, 256>>>(x);
    wg_kernel<<<NTOK / TT, NTH, WG_SMEM>>>(
        x, wg_fc1_w, wg_fc1_b, wg_fc2_w, wg_fc2_b,
        wg_glu_w, wg_glu_b, wg_skip_w, wg_skip_b, wg_ln_g, wg_ln_b, out_wts);

    fc1skip_kernel<<<ggrid, 512>>>(vg_fc1_w, vg_fc1_b, vg_skip_w, vg_skip_b);
    fc2_kernel<<<ggrid, 512>>>(vg_fc2_w, vg_fc2_b);
    glu_kernel<<<ggrid, 512, GLU_SMEM>>>(vg_glu_w, vg_glu_b, vg_ln_g, vg_ln_b, out_wts);

    combine_kernel<<<NTOK, NH>>>(out_sel);
}

// round 6
// speedup vs baseline: 2.0484x; 1.4393x over previous
#include <cuda_runtime.h>
#include <math.h>
#include <stdint.h>

// Problem constants
#define NTH   512
#define PAD   65
#define NV    16
#define ND    64
#define NH    256
#define NC    128
#define NTOK  8192
#define TT    64     // wg token tile
#define GT    128    // gemm token tile
#define BK    16     // gemm k-chunk
#define SP    132    // xt smem pad

typedef unsigned long long u64;

// Scratch (device globals: allocation-free rule)
__device__ float g_ctxp[32 * NH];
__device__ float g_xT[NV * ND * NTOK];        // x transposed [v][d][n]
__device__ float g_h1[NV * NH * NTOK];        // elu(fc1) [v][c][n]
__device__ float g_res[NV * NH * NTOK];       // skip residual [v][c][n]
__device__ float g_h2[NV * NH * NTOK];        // fc2 out [v][c][n]
__device__ float g_a[NV * NH * NTOK];         // glu a-half [v][c][n]
__device__ float g_hv[NTOK * NV * NH];        // raw hv (pre-LN) [n][v][c]

__device__ __forceinline__ float elu_f(float x)  { return x > 0.f ? x : (__expf(x) - 1.f); }
__device__ __forceinline__ float sigm_f(float x) { return 1.f / (1.f + __expf(-x)); }
__device__ __forceinline__ float idf(float x)    { return x; }

// ---- packed fp32x2 helpers ----
__device__ __forceinline__ u64 pk2(float a, float b) {
    u64 r; asm("mov.b64 %0, {%1, %2};" : "=l"(r) : "f"(a), "f"(b)); return r;
}
__device__ __forceinline__ void fm2(u64& d, u64 a, u64 b) {
    asm("fma.rn.f32x2 %0, %1, %2, %0;" : "+l"(d) : "l"(a), "l"(b));
}
__device__ __forceinline__ float2 up2(u64 v) {
    float2 f; asm("mov.b64 {%0, %1}, %2;" : "=f"(f.x), "=f"(f.y) : "l"(v)); return f;
}

// ---- cp.async helpers ----
__device__ __forceinline__ void cpa16(unsigned int s, const void* g) {
    asm volatile("cp.async.cg.shared.global [%0], [%1], 16;" :: "r"(s), "l"(g));
}
#define CPA_COMMIT() asm volatile("cp.async.commit_group;" ::: "memory")
#define CPA_WAIT(n)  asm volatile("cp.async.wait_group %0;" :: "n"(n) : "memory")

// ===========================================================================
// Tiled GEMM core: block = 128 tokens x 256 cols, 512 threads.
// Thread tile 8 tok x 8 col; acc[c][tokenpair] u64. Warp lanes share t0.
// smem: xs[2][BK][128] + ws[2][BK][256] = 48KB, cp.async double-buffered.
// ===========================================================================
#define GDECL \
    extern __shared__ float smem[]; \
    float* xs = smem; \
    float* ws = smem + 2 * BK * GT; \
    const unsigned int xs_u = (unsigned int)__cvta_generic_to_shared(xs); \
    const unsigned int ws_u = (unsigned int)__cvta_generic_to_shared(ws); \
    const int tid = threadIdx.x; \
    const int t0  = (tid >> 5) * 8; \
    const int c0  = (tid & 31) * 8; \
    const int v   = blockIdx.y; \
    const int n0  = blockIdx.x * GT; \
    u64 acc[8][4];

#define GZERO() do { \
    _Pragma("unroll") for (int _c = 0; _c < 8; ++_c) \
    _Pragma("unroll") for (int _t = 0; _t < 4; ++_t) acc[_c][_t] = 0ull; \
} while (0)

#define ISSUE(APTR, WPTR, WS_, k0, buf) do { \
    { int kr = tid >> 5, cc = tid & 31; \
      cpa16(xs_u + (((buf) * BK + kr) * GT + cc * 4) * 4, \
            (APTR) + (size_t)((k0) + kr) * NTOK + cc * 4); } \
    _Pragma("unroll") \
    for (int s2 = 0; s2 < 2; ++s2) { \
      int ci = tid + s2 * 512; int kr = ci >> 6, cc = ci & 63; \
      cpa16(ws_u + (((buf) * BK + kr) * NH + cc * 4) * 4, \
            (WPTR) + (size_t)((k0) + kr) * (WS_) + cc * 4); } \
} while (0)

#define GCHUNK(buf) do { \
    const float* xr = xs + (buf) * BK * GT + t0; \
    const float* wr = ws + (buf) * BK * NH + c0; \
    _Pragma("unroll") \
    for (int kk = 0; kk < BK; ++kk) { \
        float4 xa = *(const float4*)(xr + kk * GT); \
        float4 xb = *(const float4*)(xr + kk * GT + 4); \
        float4 wa = *(const float4*)(wr + kk * NH); \
        float4 wb = *(const float4*)(wr + kk * NH + 4); \
        u64 xp0 = pk2(xa.x, xa.y), xp1 = pk2(xa.z, xa.w); \
        u64 xp2 = pk2(xb.x, xb.y), xp3 = pk2(xb.z, xb.w); \
        u64 q; \
        q = pk2(wa.x, wa.x); fm2(acc[0][0], q, xp0); fm2(acc[0][1], q, xp1); fm2(acc[0][2], q, xp2); fm2(acc[0][3], q, xp3); \
        q = pk2(wa.y, wa.y); fm2(acc[1][0], q, xp0); fm2(acc[1][1], q, xp1); fm2(acc[1][2], q, xp2); fm2(acc[1][3], q, xp3); \
        q = pk2(wa.z, wa.z); fm2(acc[2][0], q, xp0); fm2(acc[2][1], q, xp1); fm2(acc[2][2], q, xp2); fm2(acc[2][3], q, xp3); \
        q = pk2(wa.w, wa.w); fm2(acc[3][0], q, xp0); fm2(acc[3][1], q, xp1); fm2(acc[3][2], q, xp2); fm2(acc[3][3], q, xp3); \
        q = pk2(wb.x, wb.x); fm2(acc[4][0], q, xp0); fm2(acc[4][1], q, xp1); fm2(acc[4][2], q, xp2); fm2(acc[4][3], q, xp3); \
        q = pk2(wb.y, wb.y); fm2(acc[5][0], q, xp0); fm2(acc[5][1], q, xp1); fm2(acc[5][2], q, xp2); fm2(acc[5][3], q, xp3); \
        q = pk2(wb.z, wb.z); fm2(acc[6][0], q, xp0); fm2(acc[6][1], q, xp1); fm2(acc[6][2], q, xp2); fm2(acc[6][3], q, xp3); \
        q = pk2(wb.w, wb.w); fm2(acc[7][0], q, xp0); fm2(acc[7][1], q, xp1); fm2(acc[7][2], q, xp2); fm2(acc[7][3], q, xp3); \
    } \
} while (0)

#define GRUN(APTR, WPTR, WS_, KN) do { \
    ISSUE(APTR, WPTR, WS_, 0, 0); CPA_COMMIT(); \
    for (int kc = 0; kc < (KN) / BK; ++kc) { \
        int buf = kc & 1; \
        if (kc + 1 < (KN) / BK) { \
            ISSUE(APTR, WPTR, WS_, (kc + 1) * BK, buf ^ 1); CPA_COMMIT(); CPA_WAIT(1); \
        } else { CPA_WAIT(0); } \
        __syncthreads(); \
        GCHUNK(buf); \
        __syncthreads(); \
    } \
} while (0)

// Epilogue: bias + OP, store [c][NTOK] (tokens contiguous)
#define GEPI(OUTP, BIASP, OP) do { \
    _Pragma("unroll") \
    for (int c = 0; c < 8; ++c) { \
        int col = c0 + c; float bb = (BIASP)[col]; \
        float2 p0 = up2(acc[c][0]), p1 = up2(acc[c][1]); \
        float2 p2 = up2(acc[c][2]), p3 = up2(acc[c][3]); \
        float* d = (OUTP) + (size_t)col * NTOK + n0 + t0; \
        *(float4*)d       = make_float4(OP(p0.x + bb), OP(p0.y + bb), OP(p1.x + bb), OP(p1.y + bb)); \
        *(float4*)(d + 4) = make_float4(OP(p2.x + bb), OP(p2.y + bb), OP(p3.x + bb), OP(p3.y + bb)); \
    } \
} while (0)

// ---------------------------------------------------------------------------
// Kernel 0: context projection
// ---------------------------------------------------------------------------
__global__ void ctx_kernel(const float* __restrict__ ctx, const float* __restrict__ wctx)
{
    int b = blockIdx.x;
    int h = threadIdx.x;
    float acc = 0.f;
    for (int c = 0; c < NC; ++c)
        acc += ctx[b * NC + c] * wctx[c * NH + h];
    g_ctxp[b * NH + h] = acc;
}

// ---------------------------------------------------------------------------
// Kernel: transpose x[n][v][d] -> g_xT[v][d][n]
// ---------------------------------------------------------------------------
__global__ void xt_kernel(const float* __restrict__ x)
{
    __shared__ float s[64 * SP];
    const int v  = blockIdx.y;
    const int n0 = blockIdx.x * GT;
    const int tid = threadIdx.x;

#pragma unroll
    for (int r = 0; r < 8; ++r) {
        int idx = tid + r * 256;
        int t  = idx >> 4;
        int dq = idx & 15;
        float4 val = *(const float4*)(x + (size_t)(n0 + t) * 1024 + v * 64 + dq * 4);
        s[(dq * 4 + 0) * SP + t] = val.x;
        s[(dq * 4 + 1) * SP + t] = val.y;
        s[(dq * 4 + 2) * SP + t] = val.z;
        s[(dq * 4 + 3) * SP + t] = val.w;
    }
    __syncthreads();
#pragma unroll
    for (int r = 0; r < 8; ++r) {
        int idx = tid + r * 256;
        int d  = idx >> 5;
        int tq = idx & 31;
        float4 o = *(const float4*)(s + d * SP + tq * 4);
        *(float4*)(g_xT + ((size_t)v * ND + d) * NTOK + n0 + tq * 4) = o;
    }
}

// ---------------------------------------------------------------------------
// Kernel 1: weight GRN -> softmax weights (unchanged)
// ---------------------------------------------------------------------------
#define GSTEP(ACC) do { \
    u64 _xp; \
    _xp = pk2(xs0, xs0); fm2(ACC[0][0], wA.x, _xp); fm2(ACC[0][1], wA.y, _xp); fm2(ACC[0][2], wB.x, _xp); fm2(ACC[0][3], wB.y, _xp); \
    _xp = pk2(xs1, xs1); fm2(ACC[1][0], wA.x, _xp); fm2(ACC[1][1], wA.y, _xp); fm2(ACC[1][2], wB.x, _xp); fm2(ACC[1][3], wB.y, _xp); \
    _xp = pk2(xs2, xs2); fm2(ACC[2][0], wA.x, _xp); fm2(ACC[2][1], wA.y, _xp); fm2(ACC[2][2], wB.x, _xp); fm2(ACC[2][3], wB.y, _xp); \
    _xp = pk2(xs3, xs3); fm2(ACC[3][0], wA.x, _xp); fm2(ACC[3][1], wA.y, _xp); fm2(ACC[3][2], wB.x, _xp); fm2(ACC[3][3], wB.y, _xp); \
} while (0)

#define ZERO44(ACC) do { \
    _Pragma("unroll") for (int _i = 0; _i < 4; ++_i) \
    _Pragma("unroll") for (int _j = 0; _j < 4; ++_j) ACC[_i][_j] = 0ull; \
} while (0)

__global__ __launch_bounds__(NTH, 1)
void wg_kernel(const float* __restrict__ x,
               const float* __restrict__ fc1w, const float* __restrict__ fc1b,
               const float* __restrict__ fc2w, const float* __restrict__ fc2b,
               const float* __restrict__ gluw, const float* __restrict__ glub,
               const float* __restrict__ skw,  const float* __restrict__ skb,
               const float* __restrict__ lng,  const float* __restrict__ lnb,
               float* __restrict__ outw)
{
    extern __shared__ float sm[];
    float* sx  = sm;                       // [128][PAD]
    float* ash = sx  + 128 * PAD;          // [256][PAD]
    float* bsh = ash + 256 * PAD;          // [256][PAD]
    float* rsh = bsh + 256 * PAD;          // [64][16]
    float* gsh = rsh + 64 * 16;            // [64][32]

    const int tid  = threadIdx.x;
    const int warp = tid >> 5, lane = tid & 31;
    const int t0 = warp * 4;
    const int c0 = lane * 8;
    const int n0 = blockIdx.x * TT;
    const int tR = tid >> 3, jR = tid & 7;

    u64 acc[4][4];
    ZERO44(acc);
    float r0 = 0.f, r1 = 0.f;

    for (int kt = 0; kt < 8; ++kt) {
        for (int i = tid; i < TT * 128; i += NTH) {
            int t = i >> 7, k = i & 127;
            sx[k * PAD + t] = x[(size_t)(n0 + t) * 1024 + kt * 128 + k];
        }
        __syncthreads();
        const float* W = fc1w + (size_t)(kt * 128) * NH + c0;
#pragma unroll 2
        for (int k = 0; k < 128; ++k) {
            ulonglong2 wA = *(const ulonglong2*)(W + (size_t)k * NH);
            ulonglong2 wB = *(const ulonglong2*)(W + (size_t)k * NH + 4);
            float xs0 = sx[k * PAD + t0 + 0];
            float xs1 = sx[k * PAD + t0 + 1];
            float xs2 = sx[k * PAD + t0 + 2];
            float xs3 = sx[k * PAD + t0 + 3];
            GSTEP(acc);
        }
        const float* Ws = skw + (size_t)(kt * 128) * NV;
#pragma unroll 4
        for (int k = 0; k < 128; ++k) {
            float xv = sx[k * PAD + tR];
            r0 += xv * Ws[k * NV + jR];
            r1 += xv * Ws[k * NV + jR + 8];
        }
        __syncthreads();
    }

    {
        const int b = n0 >> 8;
#pragma unroll
        for (int j = 0; j < 4; ++j) {
            int ca = c0 + 2 * j, cb = ca + 1;
            float ba = fc1b[ca] + g_ctxp[b * NH + ca];
            float bb = fc1b[cb] + g_ctxp[b * NH + cb];
#pragma unroll
            for (int i = 0; i < 4; ++i) {
                float2 p = up2(acc[i][j]);
                ash[ca * PAD + t0 + i] = elu_f(p.x + ba);
                ash[cb * PAD + t0 + i] = elu_f(p.y + bb);
            }
        }
        rsh[tR * 16 + jR]     = r0 + skb[jR];
        rsh[tR * 16 + jR + 8] = r1 + skb[jR + 8];
    }
    __syncthreads();

    ZERO44(acc);
    {
        const float* W2 = fc2w + c0;
#pragma unroll 2
        for (int k = 0; k < NH; ++k) {
            ulonglong2 wA = *(const ulonglong2*)(W2 + (size_t)k * NH);
            ulonglong2 wB = *(const ulonglong2*)(W2 + (size_t)k * NH + 4);
            float xs0 = ash[k * PAD + t0 + 0];
            float xs1 = ash[k * PAD + t0 + 1];
            float xs2 = ash[k * PAD + t0 + 2];
            float xs3 = ash[k * PAD + t0 + 3];
            GSTEP(acc);
        }
#pragma unroll
        for (int j = 0; j < 4; ++j) {
            int ca = c0 + 2 * j, cb = ca + 1;
            float ba = fc2b[ca], bb = fc2b[cb];
#pragma unroll
            for (int i = 0; i < 4; ++i) {
                float2 p = up2(acc[i][j]);
                bsh[ca * PAD + t0 + i] = p.x + ba;
                bsh[cb * PAD + t0 + i] = p.y + bb;
            }
        }
    }
    __syncthreads();

    {
        float a3[4] = {0.f, 0.f, 0.f, 0.f};
#pragma unroll 4
        for (int k = 0; k < NH; ++k) {
            float w = gluw[k * 32 + lane];
            a3[0] += bsh[k * PAD + t0 + 0] * w;
            a3[1] += bsh[k * PAD + t0 + 1] * w;
            a3[2] += bsh[k * PAD + t0 + 2] * w;
            a3[3] += bsh[k * PAD + t0 + 3] * w;
        }
        float gb = glub[lane];
#pragma unroll
        for (int i = 0; i < 4; ++i)
            gsh[(t0 + i) * 32 + lane] = a3[i] + gb;
    }
    __syncthreads();

    if (tid < TT) {
        int t = tid;
        float h[NV];
        float mu = 0.f;
#pragma unroll
        for (int v = 0; v < NV; ++v) {
            float a  = gsh[t * 32 + v];
            float bb = gsh[t * 32 + 16 + v];
            h[v] = a * sigm_f(bb) + rsh[t * 16 + v];
            mu += h[v];
        }
        mu *= (1.f / 16.f);
        float var = 0.f;
#pragma unroll
        for (int v = 0; v < NV; ++v) { float d = h[v] - mu; var += d * d; }
        var *= (1.f / 16.f);
        float rstd = rsqrtf(var + 1e-5f);
        float y[NV], m = -1e30f;
#pragma unroll
        for (int v = 0; v < NV; ++v) {
            y[v] = (h[v] - mu) * rstd * lng[v] + lnb[v];
            m = fmaxf(m, y[v]);
        }
        float s = 0.f;
#pragma unroll
        for (int v = 0; v < NV; ++v) { y[v] = __expf(y[v] - m); s += y[v]; }
        float inv = 1.f / s;
#pragma unroll
        for (int v = 0; v < NV; ++v)
            outw[(n0 + t) * NV + v] = y[v] * inv;
    }
}

// ---------------------------------------------------------------------------
// Kernel 2a: h1 = elu(x @ fc1 + b1), res = x @ skip + bs   (K = 64)
// ---------------------------------------------------------------------------
__global__ __launch_bounds__(512, 1)
void fc1skip_kernel(const float* __restrict__ fc1w, const float* __restrict__ fc1b,
                    const float* __restrict__ skw,  const float* __restrict__ skb)
{
    GDECL;
    const float* A  = g_xT + (size_t)v * ND * NTOK + n0;
    const float* W1 = fc1w + (size_t)v * ND * NH;
    const float* W2 = skw  + (size_t)v * ND * NH;

    GZERO();
    GRUN(A, W1, NH, ND);
    GEPI(g_h1 + (size_t)v * NH * NTOK, fc1b + v * NH, elu_f);

    GZERO();
    GRUN(A, W2, NH, ND);
    GEPI(g_res + (size_t)v * NH * NTOK, skb + v * NH, idf);
}

// ---------------------------------------------------------------------------
// Kernel 2b: h2 = h1 @ fc2 + b2   (K = 256)
// ---------------------------------------------------------------------------
__global__ __launch_bounds__(512, 1)
void fc2_kernel(const float* __restrict__ fc2w, const float* __restrict__ fc2b)
{
    GDECL;
    const float* A = g_h1 + (size_t)v * NH * NTOK + n0;
    const float* W = fc2w + (size_t)v * NH * NH;

    GZERO();
    GRUN(A, W, NH, NH);
    GEPI(g_h2 + (size_t)v * NH * NTOK, fc2b + v * NH, idf);
}

// ---------------------------------------------------------------------------
// Kernel 2c-1: a-half of GLU -> g_a   (K = 256)
// ---------------------------------------------------------------------------
__global__ __launch_bounds__(512, 1)
void glu_a_kernel(const float* __restrict__ gluw, const float* __restrict__ glub)
{
    GDECL;
    const float* A = g_h2 + (size_t)v * NH * NTOK + n0;
    const float* W = gluw + (size_t)v * NH * 512;

    GZERO();
    GRUN(A, W, 512, NH);
    GEPI(g_a + (size_t)v * NH * NTOK, glub + v * 512, idf);
}

// ---------------------------------------------------------------------------
// Kernel 2c-2: b-half + combine: hv = a * sigm(b) + res -> g_hv [n][v][c]
// ---------------------------------------------------------------------------
__global__ __launch_bounds__(512, 1)
void glu_b_kernel(const float* __restrict__ gluw, const float* __restrict__ glub)
{
    GDECL;
    const float* A = g_h2 + (size_t)v * NH * NTOK + n0;
    const float* W = gluw + (size_t)v * NH * 512 + 256;

    GZERO();
    GRUN(A, W, 512, NH);

    // combine: hv = a * sigm(b + bias) + res, repack into acc
#pragma unroll
    for (int c = 0; c < 8; ++c) {
        int col = c0 + c;
        float bb = glub[v * 512 + 256 + col];
        const float* ap = g_a   + ((size_t)v * NH + col) * NTOK + n0 + t0;
        const float* rp = g_res + ((size_t)v * NH + col) * NTOK + n0 + t0;
        float4 a0 = *(const float4*)ap, a1 = *(const float4*)(ap + 4);
        float4 r0 = *(const float4*)rp, r1 = *(const float4*)(rp + 4);
        float2 p0 = up2(acc[c][0]), p1 = up2(acc[c][1]);
        float2 p2 = up2(acc[c][2]), p3 = up2(acc[c][3]);
        float h0 = a0.x * sigm_f(p0.x + bb) + r0.x;
        float h1 = a0.y * sigm_f(p0.y + bb) + r0.y;
        float h2 = a0.z * sigm_f(p1.x + bb) + r0.z;
        float h3 = a0.w * sigm_f(p1.y + bb) + r0.w;
        float h4 = a1.x * sigm_f(p2.x + bb) + r1.x;
        float h5 = a1.y * sigm_f(p2.y + bb) + r1.y;
        float h6 = a1.z * sigm_f(p3.x + bb) + r1.z;
        float h7 = a1.w * sigm_f(p3.y + bb) + r1.w;
        acc[c][0] = pk2(h0, h1); acc[c][1] = pk2(h2, h3);
        acc[c][2] = pk2(h4, h5); acc[c][3] = pk2(h6, h7);
    }

    // transpose store: per token, cols contiguous -> g_hv[n][v][c]
#pragma unroll
    for (int tp = 0; tp < 4; ++tp) {
        float2 q0 = up2(acc[0][tp]), q1 = up2(acc[1][tp]);
        float2 q2 = up2(acc[2][tp]), q3 = up2(acc[3][tp]);
        float2 q4 = up2(acc[4][tp]), q5 = up2(acc[5][tp]);
        float2 q6 = up2(acc[6][tp]), q7 = up2(acc[7][tp]);
        float* dA = g_hv + (size_t)(n0 + t0 + 2 * tp)     * (NV * NH) + v * NH + c0;
        float* dB = g_hv + (size_t)(n0 + t0 + 2 * tp + 1) * (NV * NH) + v * NH + c0;
        *(float4*)dA       = make_float4(q0.x, q1.x, q2.x, q3.x);
        *(float4*)(dA + 4) = make_float4(q4.x, q5.x, q6.x, q7.x);
        *(float4*)dB       = make_float4(q0.y, q1.y, q2.y, q3.y);
        *(float4*)(dB + 4) = make_float4(q4.y, q5.y, q6.y, q7.y);
    }
}

// ---------------------------------------------------------------------------
// Kernel 3: per-token LN(256) per v + weight scale + sum over v -> selected
// ---------------------------------------------------------------------------
__global__ void combine_kernel(const float* __restrict__ lng, const float* __restrict__ lnb,
                               const float* __restrict__ wts, float* __restrict__ out_sel)
{
    __shared__ float s_part[8 * 260];
    const int n = blockIdx.x;
    const int tid = threadIdx.x;
    const int w = tid >> 5, lane = tid & 31;

    float psum[8];
#pragma unroll
    for (int j = 0; j < 8; ++j) psum[j] = 0.f;

#pragma unroll
    for (int vv = 0; vv < 2; ++vv) {
        int v = w * 2 + vv;
        const float* p = g_hv + (size_t)n * (NV * NH) + v * NH + lane * 8;
        float4 u0 = *(const float4*)p, u1 = *(const float4*)(p + 4);
        float uu[8] = {u0.x, u0.y, u0.z, u0.w, u1.x, u1.y, u1.z, u1.w};
        float s = 0.f, s2 = 0.f;
#pragma unroll
        for (int j = 0; j < 8; ++j) { s += uu[j]; s2 += uu[j] * uu[j]; }
#pragma unroll
        for (int off = 16; off > 0; off >>= 1) {
            s  += __shfl_xor_sync(0xffffffffu, s,  off);
            s2 += __shfl_xor_sync(0xffffffffu, s2, off);
        }
        float mu   = s * (1.f / 256.f);
        float var  = s2 * (1.f / 256.f) - mu * mu;
        float rstd = rsqrtf(var + 1e-5f);
        float wv = wts[n * NV + v];
#pragma unroll
        for (int j = 0; j < 8; ++j) {
            int c = lane * 8 + j;
            float y = (uu[j] - mu) * rstd * lng[v * NH + c] + lnb[v * NH + c];
            psum[j] += y * wv;
        }
    }

    *(float4*)(s_part + w * 260 + lane * 8)     = make_float4(psum[0], psum[1], psum[2], psum[3]);
    *(float4*)(s_part + w * 260 + lane * 8 + 4) = make_float4(psum[4], psum[5], psum[6], psum[7]);
    __syncthreads();

    float s = 0.f;
#pragma unroll
    for (int w8 = 0; w8 < 8; ++w8) s += s_part[w8 * 260 + tid];
    out_sel[(size_t)n * NH + tid] = s;
}

// ---------------------------------------------------------------------------
extern "C" void kernel_launch(void* const* d_in, const int* in_sizes, int n_in,
                              void* d_out, int out_size)
{
    const float* x        = (const float*)d_in[0];
    const float* context  = (const float*)d_in[1];
    const float* vg_fc1_w = (const float*)d_in[2];
    const float* vg_fc1_b = (const float*)d_in[3];
    const float* vg_fc2_w = (const float*)d_in[4];
    const float* vg_fc2_b = (const float*)d_in[5];
    const float* vg_glu_w = (const float*)d_in[6];
    const float* vg_glu_b = (const float*)d_in[7];
    const float* vg_skip_w= (const float*)d_in[8];
    const float* vg_skip_b= (const float*)d_in[9];
    const float* vg_ln_g  = (const float*)d_in[10];
    const float* vg_ln_b  = (const float*)d_in[11];
    const float* wg_fc1_w = (const float*)d_in[12];
    const float* wg_fc1_b = (const float*)d_in[13];
    const float* wg_ctx_w = (const float*)d_in[14];
    const float* wg_fc2_w = (const float*)d_in[15];
    const float* wg_fc2_b = (const float*)d_in[16];
    const float* wg_glu_w = (const float*)d_in[17];
    const float* wg_glu_b = (const float*)d_in[18];
    const float* wg_skip_w= (const float*)d_in[19];
    const float* wg_skip_b= (const float*)d_in[20];
    const float* wg_ln_g  = (const float*)d_in[21];
    const float* wg_ln_b  = (const float*)d_in[22];

    float* out      = (float*)d_out;
    float* out_sel  = out;
    float* out_wts  = out + (size_t)NTOK * NH;

    const int WG_SMEM = (128 * PAD + 2 * 256 * PAD + 64 * 16 + 64 * 32) * 4;
    const int G_SMEM  = (2 * BK * GT + 2 * BK * NH) * 4;   // 48KB
    cudaFuncSetAttribute(wg_kernel,      cudaFuncAttributeMaxDynamicSharedMemorySize, WG_SMEM);
    cudaFuncSetAttribute(fc1skip_kernel, cudaFuncAttributeMaxDynamicSharedMemorySize, G_SMEM);
    cudaFuncSetAttribute(fc2_kernel,     cudaFuncAttributeMaxDynamicSharedMemorySize, G_SMEM);
    cudaFuncSetAttribute(glu_a_kernel,   cudaFuncAttributeMaxDynamicSharedMemorySize, G_SMEM);
    cudaFuncSetAttribute(glu_b_kernel,   cudaFuncAttributeMaxDynamicSharedMemorySize, G_SMEM);

    const dim3 ggrid(NTOK / GT, NV);

    ctx_kernel<<<32, NH>>>(context, wg_ctx_w);
    xt_kernel<<<ggrid, 256>>>(x);
    wg_kernel<<<NTOK / TT, NTH, WG_SMEM>>>(
        x, wg_fc1_w, wg_fc1_b, wg_fc2_w, wg_fc2_b,
        wg_glu_w, wg_glu_b, wg_skip_w, wg_skip_b, wg_ln_g, wg_ln_b, out_wts);

    fc1skip_kernel<<<ggrid, 512, G_SMEM>>>(vg_fc1_w, vg_fc1_b, vg_skip_w, vg_skip_b);
    fc2_kernel<<<ggrid, 512, G_SMEM>>>(vg_fc2_w, vg_fc2_b);
    glu_a_kernel<<<ggrid, 512, G_SMEM>>>(vg_glu_w, vg_glu_b);
    glu_b_kernel<<<ggrid, 512, G_SMEM>>>(vg_glu_w, vg_glu_b);

    combine_kernel<<<NTOK, 256>>>(vg_ln_g, vg_ln_b, out_wts, out_sel);
}

// round 7
// speedup vs baseline: 2.2122x; 1.0799x over previous
#include <cuda_runtime.h>
#include <math.h>
#include <stdint.h>

// Problem constants
#define NTH   512
#define PAD   65
#define NV    16
#define ND    64
#define NH    256
#define NC    128
#define NTOK  8192
#define TT    64     // wg token tile
#define GT    128    // xt token tile
#define GTOK  64     // gemm token tile
#define BK    16     // gemm k-chunk
#define NS    4      // pipeline stages
#define SP    132    // xt smem pad

typedef unsigned long long u64;

// Scratch (device globals: allocation-free rule)
__device__ float g_ctxp[32 * NH];
__device__ float g_xT[NV * ND * NTOK];        // x transposed [v][d][n]
__device__ float g_h1[NV * NH * NTOK];        // elu(fc1) [v][c][n]
__device__ float g_res[NV * NH * NTOK];       // skip residual [v][c][n]
__device__ float g_h2[NV * NH * NTOK];        // fc2 out [v][c][n]
__device__ float g_a[NV * NH * NTOK];         // glu a-half [v][c][n]
__device__ float g_hv[NTOK * NV * NH];        // raw hv (pre-LN) [n][v][c]

__device__ __forceinline__ float elu_f(float x)  { return x > 0.f ? x : (__expf(x) - 1.f); }
__device__ __forceinline__ float sigm_f(float x) { return 1.f / (1.f + __expf(-x)); }
__device__ __forceinline__ float idf(float x)    { return x; }

// ---- packed fp32x2 helpers ----
__device__ __forceinline__ u64 pk2(float a, float b) {
    u64 r; asm("mov.b64 %0, {%1, %2};" : "=l"(r) : "f"(a), "f"(b)); return r;
}
__device__ __forceinline__ void fm2(u64& d, u64 a, u64 b) {
    asm("fma.rn.f32x2 %0, %1, %2, %0;" : "+l"(d) : "l"(a), "l"(b));
}
__device__ __forceinline__ float2 up2(u64 v) {
    float2 f; asm("mov.b64 {%0, %1}, %2;" : "=f"(f.x), "=f"(f.y) : "l"(v)); return f;
}

// ---- cp.async helpers ----
__device__ __forceinline__ void cpa16(unsigned int s, const void* g) {
    asm volatile("cp.async.cg.shared.global [%0], [%1], 16;" :: "r"(s), "l"(g));
}
#define CPA_COMMIT() asm volatile("cp.async.commit_group;" ::: "memory")
#define CPA_WAIT(n)  asm volatile("cp.async.wait_group %0;" :: "n"(n) : "memory")

// ===========================================================================
// Tiled GEMM core v2: block = 64 tokens x 256 cols, 256 threads, 2 blocks/SM.
// Thread tile 8 tok x 8 col; warp lanes share t0 (x broadcast), c0 per-lane.
// smem: NS stages of xs[BK][64] + ws[BK][256] = 80KB. 1 barrier per chunk.
// ===========================================================================
#define GDECL \
    extern __shared__ float smem[]; \
    float* xs = smem; \
    float* ws = smem + NS * BK * GTOK; \
    const unsigned int xs_u = (unsigned int)__cvta_generic_to_shared(xs); \
    const unsigned int ws_u = (unsigned int)__cvta_generic_to_shared(ws); \
    const int tid = threadIdx.x; \
    const int t0  = (tid >> 5) * 8; \
    const int c0  = (tid & 31) * 8; \
    const int v   = blockIdx.y; \
    const int n0  = blockIdx.x * GTOK; \
    u64 acc[8][4];

#define GZERO() do { \
    _Pragma("unroll") for (int _c = 0; _c < 8; ++_c) \
    _Pragma("unroll") for (int _t = 0; _t < 4; ++_t) acc[_c][_t] = 0ull; \
} while (0)

// x: 16 rows x 64 floats = 4KB = 256 cpa16 (1/thread)
// w: 16 rows x 256 floats = 16KB = 1024 cpa16 (4/thread)
#define ISSUE(APTR, WPTR, WS_, k0, buf) do { \
    { int kr = tid >> 4, cc = tid & 15; \
      cpa16(xs_u + (((buf) * BK + kr) * GTOK + cc * 4) * 4, \
            (APTR) + (size_t)((k0) + kr) * NTOK + cc * 4); } \
    _Pragma("unroll") \
    for (int s2 = 0; s2 < 4; ++s2) { \
      int ci = tid + s2 * 256; int kr = ci >> 6, cc = ci & 63; \
      cpa16(ws_u + (((buf) * BK + kr) * NH + cc * 4) * 4, \
            (WPTR) + (size_t)((k0) + kr) * (WS_) + cc * 4); } \
} while (0)

#define GCHUNK(buf) do { \
    const float* xr = xs + (buf) * BK * GTOK + t0; \
    const float* wr = ws + (buf) * BK * NH + c0; \
    _Pragma("unroll") \
    for (int kk = 0; kk < BK; ++kk) { \
        float4 xa = *(const float4*)(xr + kk * GTOK); \
        float4 xb = *(const float4*)(xr + kk * GTOK + 4); \
        float4 wa = *(const float4*)(wr + kk * NH); \
        float4 wb = *(const float4*)(wr + kk * NH + 4); \
        u64 xp0 = pk2(xa.x, xa.y), xp1 = pk2(xa.z, xa.w); \
        u64 xp2 = pk2(xb.x, xb.y), xp3 = pk2(xb.z, xb.w); \
        u64 q; \
        q = pk2(wa.x, wa.x); fm2(acc[0][0], q, xp0); fm2(acc[0][1], q, xp1); fm2(acc[0][2], q, xp2); fm2(acc[0][3], q, xp3); \
        q = pk2(wa.y, wa.y); fm2(acc[1][0], q, xp0); fm2(acc[1][1], q, xp1); fm2(acc[1][2], q, xp2); fm2(acc[1][3], q, xp3); \
        q = pk2(wa.z, wa.z); fm2(acc[2][0], q, xp0); fm2(acc[2][1], q, xp1); fm2(acc[2][2], q, xp2); fm2(acc[2][3], q, xp3); \
        q = pk2(wa.w, wa.w); fm2(acc[3][0], q, xp0); fm2(acc[3][1], q, xp1); fm2(acc[3][2], q, xp2); fm2(acc[3][3], q, xp3); \
        q = pk2(wb.x, wb.x); fm2(acc[4][0], q, xp0); fm2(acc[4][1], q, xp1); fm2(acc[4][2], q, xp2); fm2(acc[4][3], q, xp3); \
        q = pk2(wb.y, wb.y); fm2(acc[5][0], q, xp0); fm2(acc[5][1], q, xp1); fm2(acc[5][2], q, xp2); fm2(acc[5][3], q, xp3); \
        q = pk2(wb.z, wb.z); fm2(acc[6][0], q, xp0); fm2(acc[6][1], q, xp1); fm2(acc[6][2], q, xp2); fm2(acc[6][3], q, xp3); \
        q = pk2(wb.w, wb.w); fm2(acc[7][0], q, xp0); fm2(acc[7][1], q, xp1); fm2(acc[7][2], q, xp2); fm2(acc[7][3], q, xp3); \
    } \
} while (0)

// 4-deep pipeline, one barrier per chunk. Issue into buffer (kc-1)%NS whose
// consumption was fenced by the PREVIOUS chunk's barrier.
#define GRUN(APTR, WPTR, WS_, KN) do { \
    const int nkc = (KN) / BK; \
    _Pragma("unroll") \
    for (int p = 0; p < NS - 1; ++p) { \
        if (p < nkc) { ISSUE(APTR, WPTR, WS_, p * BK, p); CPA_COMMIT(); } \
    } \
    for (int kc = 0; kc < nkc; ++kc) { \
        CPA_WAIT(NS - 2); \
        __syncthreads(); \
        if (kc + NS - 1 < nkc) { \
            ISSUE(APTR, WPTR, WS_, (kc + NS - 1) * BK, (kc + NS - 1) % NS); \
            CPA_COMMIT(); \
        } \
        GCHUNK(kc % NS); \
    } \
} while (0)

// Epilogue: bias + OP, store [c][NTOK] (tokens contiguous)
#define GEPI(OUTP, BIASP, OP) do { \
    _Pragma("unroll") \
    for (int c = 0; c < 8; ++c) { \
        int col = c0 + c; float bb = (BIASP)[col]; \
        float2 p0 = up2(acc[c][0]), p1 = up2(acc[c][1]); \
        float2 p2 = up2(acc[c][2]), p3 = up2(acc[c][3]); \
        float* d = (OUTP) + (size_t)col * NTOK + n0 + t0; \
        *(float4*)d       = make_float4(OP(p0.x + bb), OP(p0.y + bb), OP(p1.x + bb), OP(p1.y + bb)); \
        *(float4*)(d + 4) = make_float4(OP(p2.x + bb), OP(p2.y + bb), OP(p3.x + bb), OP(p3.y + bb)); \
    } \
} while (0)

// ---------------------------------------------------------------------------
// Kernel 0: context projection
// ---------------------------------------------------------------------------
__global__ void ctx_kernel(const float* __restrict__ ctx, const float* __restrict__ wctx)
{
    int b = blockIdx.x;
    int h = threadIdx.x;
    float acc = 0.f;
    for (int c = 0; c < NC; ++c)
        acc += ctx[b * NC + c] * wctx[c * NH + h];
    g_ctxp[b * NH + h] = acc;
}

// ---------------------------------------------------------------------------
// Kernel: transpose x[n][v][d] -> g_xT[v][d][n]
// ---------------------------------------------------------------------------
__global__ void xt_kernel(const float* __restrict__ x)
{
    __shared__ float s[64 * SP];
    const int v  = blockIdx.y;
    const int n0 = blockIdx.x * GT;
    const int tid = threadIdx.x;

#pragma unroll
    for (int r = 0; r < 8; ++r) {
        int idx = tid + r * 256;
        int t  = idx >> 4;
        int dq = idx & 15;
        float4 val = *(const float4*)(x + (size_t)(n0 + t) * 1024 + v * 64 + dq * 4);
        s[(dq * 4 + 0) * SP + t] = val.x;
        s[(dq * 4 + 1) * SP + t] = val.y;
        s[(dq * 4 + 2) * SP + t] = val.z;
        s[(dq * 4 + 3) * SP + t] = val.w;
    }
    __syncthreads();
#pragma unroll
    for (int r = 0; r < 8; ++r) {
        int idx = tid + r * 256;
        int d  = idx >> 5;
        int tq = idx & 31;
        float4 o = *(const float4*)(s + d * SP + tq * 4);
        *(float4*)(g_xT + ((size_t)v * ND + d) * NTOK + n0 + tq * 4) = o;
    }
}

// ---------------------------------------------------------------------------
// Kernel 1: weight GRN -> softmax weights (unchanged)
// ---------------------------------------------------------------------------
#define GSTEP(ACC) do { \
    u64 _xp; \
    _xp = pk2(xs0, xs0); fm2(ACC[0][0], wA.x, _xp); fm2(ACC[0][1], wA.y, _xp); fm2(ACC[0][2], wB.x, _xp); fm2(ACC[0][3], wB.y, _xp); \
    _xp = pk2(xs1, xs1); fm2(ACC[1][0], wA.x, _xp); fm2(ACC[1][1], wA.y, _xp); fm2(ACC[1][2], wB.x, _xp); fm2(ACC[1][3], wB.y, _xp); \
    _xp = pk2(xs2, xs2); fm2(ACC[2][0], wA.x, _xp); fm2(ACC[2][1], wA.y, _xp); fm2(ACC[2][2], wB.x, _xp); fm2(ACC[2][3], wB.y, _xp); \
    _xp = pk2(xs3, xs3); fm2(ACC[3][0], wA.x, _xp); fm2(ACC[3][1], wA.y, _xp); fm2(ACC[3][2], wB.x, _xp); fm2(ACC[3][3], wB.y, _xp); \
} while (0)

#define ZERO44(ACC) do { \
    _Pragma("unroll") for (int _i = 0; _i < 4; ++_i) \
    _Pragma("unroll") for (int _j = 0; _j < 4; ++_j) ACC[_i][_j] = 0ull; \
} while (0)

__global__ __launch_bounds__(NTH, 1)
void wg_kernel(const float* __restrict__ x,
               const float* __restrict__ fc1w, const float* __restrict__ fc1b,
               const float* __restrict__ fc2w, const float* __restrict__ fc2b,
               const float* __restrict__ gluw, const float* __restrict__ glub,
               const float* __restrict__ skw,  const float* __restrict__ skb,
               const float* __restrict__ lng,  const float* __restrict__ lnb,
               float* __restrict__ outw)
{
    extern __shared__ float sm[];
    float* sx  = sm;                       // [128][PAD]
    float* ash = sx  + 128 * PAD;          // [256][PAD]
    float* bsh = ash + 256 * PAD;          // [256][PAD]
    float* rsh = bsh + 256 * PAD;          // [64][16]
    float* gsh = rsh + 64 * 16;            // [64][32]

    const int tid  = threadIdx.x;
    const int warp = tid >> 5, lane = tid & 31;
    const int t0 = warp * 4;
    const int c0 = lane * 8;
    const int n0 = blockIdx.x * TT;
    const int tR = tid >> 3, jR = tid & 7;

    u64 acc[4][4];
    ZERO44(acc);
    float r0 = 0.f, r1 = 0.f;

    for (int kt = 0; kt < 8; ++kt) {
        for (int i = tid; i < TT * 128; i += NTH) {
            int t = i >> 7, k = i & 127;
            sx[k * PAD + t] = x[(size_t)(n0 + t) * 1024 + kt * 128 + k];
        }
        __syncthreads();
        const float* W = fc1w + (size_t)(kt * 128) * NH + c0;
#pragma unroll 2
        for (int k = 0; k < 128; ++k) {
            ulonglong2 wA = *(const ulonglong2*)(W + (size_t)k * NH);
            ulonglong2 wB = *(const ulonglong2*)(W + (size_t)k * NH + 4);
            float xs0 = sx[k * PAD + t0 + 0];
            float xs1 = sx[k * PAD + t0 + 1];
            float xs2 = sx[k * PAD + t0 + 2];
            float xs3 = sx[k * PAD + t0 + 3];
            GSTEP(acc);
        }
        const float* Ws = skw + (size_t)(kt * 128) * NV;
#pragma unroll 4
        for (int k = 0; k < 128; ++k) {
            float xv = sx[k * PAD + tR];
            r0 += xv * Ws[k * NV + jR];
            r1 += xv * Ws[k * NV + jR + 8];
        }
        __syncthreads();
    }

    {
        const int b = n0 >> 8;
#pragma unroll
        for (int j = 0; j < 4; ++j) {
            int ca = c0 + 2 * j, cb = ca + 1;
            float ba = fc1b[ca] + g_ctxp[b * NH + ca];
            float bb = fc1b[cb] + g_ctxp[b * NH + cb];
#pragma unroll
            for (int i = 0; i < 4; ++i) {
                float2 p = up2(acc[i][j]);
                ash[ca * PAD + t0 + i] = elu_f(p.x + ba);
                ash[cb * PAD + t0 + i] = elu_f(p.y + bb);
            }
        }
        rsh[tR * 16 + jR]     = r0 + skb[jR];
        rsh[tR * 16 + jR + 8] = r1 + skb[jR + 8];
    }
    __syncthreads();

    ZERO44(acc);
    {
        const float* W2 = fc2w + c0;
#pragma unroll 2
        for (int k = 0; k < NH; ++k) {
            ulonglong2 wA = *(const ulonglong2*)(W2 + (size_t)k * NH);
            ulonglong2 wB = *(const ulonglong2*)(W2 + (size_t)k * NH + 4);
            float xs0 = ash[k * PAD + t0 + 0];
            float xs1 = ash[k * PAD + t0 + 1];
            float xs2 = ash[k * PAD + t0 + 2];
            float xs3 = ash[k * PAD + t0 + 3];
            GSTEP(acc);
        }
#pragma unroll
        for (int j = 0; j < 4; ++j) {
            int ca = c0 + 2 * j, cb = ca + 1;
            float ba = fc2b[ca], bb = fc2b[cb];
#pragma unroll
            for (int i = 0; i < 4; ++i) {
                float2 p = up2(acc[i][j]);
                bsh[ca * PAD + t0 + i] = p.x + ba;
                bsh[cb * PAD + t0 + i] = p.y + bb;
            }
        }
    }
    __syncthreads();

    {
        float a3[4] = {0.f, 0.f, 0.f, 0.f};
#pragma unroll 4
        for (int k = 0; k < NH; ++k) {
            float w = gluw[k * 32 + lane];
            a3[0] += bsh[k * PAD + t0 + 0] * w;
            a3[1] += bsh[k * PAD + t0 + 1] * w;
            a3[2] += bsh[k * PAD + t0 + 2] * w;
            a3[3] += bsh[k * PAD + t0 + 3] * w;
        }
        float gb = glub[lane];
#pragma unroll
        for (int i = 0; i < 4; ++i)
            gsh[(t0 + i) * 32 + lane] = a3[i] + gb;
    }
    __syncthreads();

    if (tid < TT) {
        int t = tid;
        float h[NV];
        float mu = 0.f;
#pragma unroll
        for (int v = 0; v < NV; ++v) {
            float a  = gsh[t * 32 + v];
            float bb = gsh[t * 32 + 16 + v];
            h[v] = a * sigm_f(bb) + rsh[t * 16 + v];
            mu += h[v];
        }
        mu *= (1.f / 16.f);
        float var = 0.f;
#pragma unroll
        for (int v = 0; v < NV; ++v) { float d = h[v] - mu; var += d * d; }
        var *= (1.f / 16.f);
        float rstd = rsqrtf(var + 1e-5f);
        float y[NV], m = -1e30f;
#pragma unroll
        for (int v = 0; v < NV; ++v) {
            y[v] = (h[v] - mu) * rstd * lng[v] + lnb[v];
            m = fmaxf(m, y[v]);
        }
        float s = 0.f;
#pragma unroll
        for (int v = 0; v < NV; ++v) { y[v] = __expf(y[v] - m); s += y[v]; }
        float inv = 1.f / s;
#pragma unroll
        for (int v = 0; v < NV; ++v)
            outw[(n0 + t) * NV + v] = y[v] * inv;
    }
}

// ---------------------------------------------------------------------------
// Kernel 2a: h1 = elu(x @ fc1 + b1), res = x @ skip + bs   (K = 64)
// ---------------------------------------------------------------------------
__global__ __launch_bounds__(256, 2)
void fc1skip_kernel(const float* __restrict__ fc1w, const float* __restrict__ fc1b,
                    const float* __restrict__ skw,  const float* __restrict__ skb)
{
    GDECL;
    const float* A  = g_xT + (size_t)v * ND * NTOK + n0;
    const float* W1 = fc1w + (size_t)v * ND * NH;
    const float* W2 = skw  + (size_t)v * ND * NH;

    GZERO();
    GRUN(A, W1, NH, ND);
    GEPI(g_h1 + (size_t)v * NH * NTOK, fc1b + v * NH, elu_f);

    GZERO();
    GRUN(A, W2, NH, ND);
    GEPI(g_res + (size_t)v * NH * NTOK, skb + v * NH, idf);
}

// ---------------------------------------------------------------------------
// Kernel 2b: h2 = h1 @ fc2 + b2   (K = 256)
// ---------------------------------------------------------------------------
__global__ __launch_bounds__(256, 2)
void fc2_kernel(const float* __restrict__ fc2w, const float* __restrict__ fc2b)
{
    GDECL;
    const float* A = g_h1 + (size_t)v * NH * NTOK + n0;
    const float* W = fc2w + (size_t)v * NH * NH;

    GZERO();
    GRUN(A, W, NH, NH);
    GEPI(g_h2 + (size_t)v * NH * NTOK, fc2b + v * NH, idf);
}

// ---------------------------------------------------------------------------
// Kernel 2c-1: a-half of GLU -> g_a   (K = 256)
// ---------------------------------------------------------------------------
__global__ __launch_bounds__(256, 2)
void glu_a_kernel(const float* __restrict__ gluw, const float* __restrict__ glub)
{
    GDECL;
    const float* A = g_h2 + (size_t)v * NH * NTOK + n0;
    const float* W = gluw + (size_t)v * NH * 512;

    GZERO();
    GRUN(A, W, 512, NH);
    GEPI(g_a + (size_t)v * NH * NTOK, glub + v * 512, idf);
}

// ---------------------------------------------------------------------------
// Kernel 2c-2: b-half + combine: hv = a * sigm(b) + res -> g_hv [n][v][c]
// ---------------------------------------------------------------------------
__global__ __launch_bounds__(256, 2)
void glu_b_kernel(const float* __restrict__ gluw, const float* __restrict__ glub)
{
    GDECL;
    const float* A = g_h2 + (size_t)v * NH * NTOK + n0;
    const float* W = gluw + (size_t)v * NH * 512 + 256;

    GZERO();
    GRUN(A, W, 512, NH);

    // combine: hv = a * sigm(b + bias) + res, repack into acc
#pragma unroll
    for (int c = 0; c < 8; ++c) {
        int col = c0 + c;
        float bb = glub[v * 512 + 256 + col];
        const float* ap = g_a   + ((size_t)v * NH + col) * NTOK + n0 + t0;
        const float* rp = g_res + ((size_t)v * NH + col) * NTOK + n0 + t0;
        float4 a0 = *(const float4*)ap, a1 = *(const float4*)(ap + 4);
        float4 r0 = *(const float4*)rp, r1 = *(const float4*)(rp + 4);
        float2 p0 = up2(acc[c][0]), p1 = up2(acc[c][1]);
        float2 p2 = up2(acc[c][2]), p3 = up2(acc[c][3]);
        float h0 = a0.x * sigm_f(p0.x + bb) + r0.x;
        float h1 = a0.y * sigm_f(p0.y + bb) + r0.y;
        float h2 = a0.z * sigm_f(p1.x + bb) + r0.z;
        float h3 = a0.w * sigm_f(p1.y + bb) + r0.w;
        float h4 = a1.x * sigm_f(p2.x + bb) + r1.x;
        float h5 = a1.y * sigm_f(p2.y + bb) + r1.y;
        float h6 = a1.z * sigm_f(p3.x + bb) + r1.z;
        float h7 = a1.w * sigm_f(p3.y + bb) + r1.w;
        acc[c][0] = pk2(h0, h1); acc[c][1] = pk2(h2, h3);
        acc[c][2] = pk2(h4, h5); acc[c][3] = pk2(h6, h7);
    }

    // transpose store: per token, cols contiguous -> g_hv[n][v][c]
#pragma unroll
    for (int tp = 0; tp < 4; ++tp) {
        float2 q0 = up2(acc[0][tp]), q1 = up2(acc[1][tp]);
        float2 q2 = up2(acc[2][tp]), q3 = up2(acc[3][tp]);
        float2 q4 = up2(acc[4][tp]), q5 = up2(acc[5][tp]);
        float2 q6 = up2(acc[6][tp]), q7 = up2(acc[7][tp]);
        float* dA = g_hv + (size_t)(n0 + t0 + 2 * tp)     * (NV * NH) + v * NH + c0;
        float* dB = g_hv + (size_t)(n0 + t0 + 2 * tp + 1) * (NV * NH) + v * NH + c0;
        *(float4*)dA       = make_float4(q0.x, q1.x, q2.x, q3.x);
        *(float4*)(dA + 4) = make_float4(q4.x, q5.x, q6.x, q7.x);
        *(float4*)dB       = make_float4(q0.y, q1.y, q2.y, q3.y);
        *(float4*)(dB + 4) = make_float4(q4.y, q5.y, q6.y, q7.y);
    }
}

// ---------------------------------------------------------------------------
// Kernel 3: per-token LN(256) per v + weight scale + sum over v -> selected
// ---------------------------------------------------------------------------
__global__ void combine_kernel(const float* __restrict__ lng, const float* __restrict__ lnb,
                               const float* __restrict__ wts, float* __restrict__ out_sel)
{
    __shared__ float s_part[8 * 260];
    const int n = blockIdx.x;
    const int tid = threadIdx.x;
    const int w = tid >> 5, lane = tid & 31;

    float psum[8];
#pragma unroll
    for (int j = 0; j < 8; ++j) psum[j] = 0.f;

#pragma unroll
    for (int vv = 0; vv < 2; ++vv) {
        int v = w * 2 + vv;
        const float* p = g_hv + (size_t)n * (NV * NH) + v * NH + lane * 8;
        float4 u0 = *(const float4*)p, u1 = *(const float4*)(p + 4);
        float uu[8] = {u0.x, u0.y, u0.z, u0.w, u1.x, u1.y, u1.z, u1.w};
        float s = 0.f, s2 = 0.f;
#pragma unroll
        for (int j = 0; j < 8; ++j) { s += uu[j]; s2 += uu[j] * uu[j]; }
#pragma unroll
        for (int off = 16; off > 0; off >>= 1) {
            s  += __shfl_xor_sync(0xffffffffu, s,  off);
            s2 += __shfl_xor_sync(0xffffffffu, s2, off);
        }
        float mu   = s * (1.f / 256.f);
        float var  = s2 * (1.f / 256.f) - mu * mu;
        float rstd = rsqrtf(var + 1e-5f);
        float wv = wts[n * NV + v];
#pragma unroll
        for (int j = 0; j < 8; ++j) {
            int c = lane * 8 + j;
            float y = (uu[j] - mu) * rstd * lng[v * NH + c] + lnb[v * NH + c];
            psum[j] += y * wv;
        }
    }

    *(float4*)(s_part + w * 260 + lane * 8)     = make_float4(psum[0], psum[1], psum[2], psum[3]);
    *(float4*)(s_part + w * 260 + lane * 8 + 4) = make_float4(psum[4], psum[5], psum[6], psum[7]);
    __syncthreads();

    float s = 0.f;
#pragma unroll
    for (int w8 = 0; w8 < 8; ++w8) s += s_part[w8 * 260 + tid];
    out_sel[(size_t)n * NH + tid] = s;
}

// ---------------------------------------------------------------------------
extern "C" void kernel_launch(void* const* d_in, const int* in_sizes, int n_in,
                              void* d_out, int out_size)
{
    const float* x        = (const float*)d_in[0];
    const float* context  = (const float*)d_in[1];
    const float* vg_fc1_w = (const float*)d_in[2];
    const float* vg_fc1_b = (const float*)d_in[3];
    const float* vg_fc2_w = (const float*)d_in[4];
    const float* vg_fc2_b = (const float*)d_in[5];
    const float* vg_glu_w = (const float*)d_in[6];
    const float* vg_glu_b = (const float*)d_in[7];
    const float* vg_skip_w= (const float*)d_in[8];
    const float* vg_skip_b= (const float*)d_in[9];
    const float* vg_ln_g  = (const float*)d_in[10];
    const float* vg_ln_b  = (const float*)d_in[11];
    const float* wg_fc1_w = (const float*)d_in[12];
    const float* wg_fc1_b = (const float*)d_in[13];
    const float* wg_ctx_w = (const float*)d_in[14];
    const float* wg_fc2_w = (const float*)d_in[15];
    const float* wg_fc2_b = (const float*)d_in[16];
    const float* wg_glu_w = (const float*)d_in[17];
    const float* wg_glu_b = (const float*)d_in[18];
    const float* wg_skip_w= (const float*)d_in[19];
    const float* wg_skip_b= (const float*)d_in[20];
    const float* wg_ln_g  = (const float*)d_in[21];
    const float* wg_ln_b  = (const float*)d_in[22];

    float* out      = (float*)d_out;
    float* out_sel  = out;
    float* out_wts  = out + (size_t)NTOK * NH;

    const int WG_SMEM = (128 * PAD + 2 * 256 * PAD + 64 * 16 + 64 * 32) * 4;
    const int G_SMEM  = NS * BK * (GTOK + NH) * 4;   // 80KB/block
    cudaFuncSetAttribute(wg_kernel,      cudaFuncAttributeMaxDynamicSharedMemorySize, WG_SMEM);
    cudaFuncSetAttribute(fc1skip_kernel, cudaFuncAttributeMaxDynamicSharedMemorySize, G_SMEM);
    cudaFuncSetAttribute(fc2_kernel,     cudaFuncAttributeMaxDynamicSharedMemorySize, G_SMEM);
    cudaFuncSetAttribute(glu_a_kernel,   cudaFuncAttributeMaxDynamicSharedMemorySize, G_SMEM);
    cudaFuncSetAttribute(glu_b_kernel,   cudaFuncAttributeMaxDynamicSharedMemorySize, G_SMEM);

    const dim3 xgrid(NTOK / GT, NV);
    const dim3 ggrid(NTOK / GTOK, NV);

    ctx_kernel<<<32, NH>>>(context, wg_ctx_w);
    xt_kernel<<<xgrid, 256>>>(x);
    wg_kernel<<<NTOK / TT, NTH, WG_SMEM>>>(
        x, wg_fc1_w, wg_fc1_b, wg_fc2_w, wg_fc2_b,
        wg_glu_w, wg_glu_b, wg_skip_w, wg_skip_b, wg_ln_g, wg_ln_b, out_wts);

    fc1skip_kernel<<<ggrid, 256, G_SMEM>>>(vg_fc1_w, vg_fc1_b, vg_skip_w, vg_skip_b);
    fc2_kernel<<<ggrid, 256, G_SMEM>>>(vg_fc2_w, vg_fc2_b);
    glu_a_kernel<<<ggrid, 256, G_SMEM>>>(vg_glu_w, vg_glu_b);
    glu_b_kernel<<<ggrid, 256, G_SMEM>>>(vg_glu_w, vg_glu_b);

    combine_kernel<<<NTOK, 256>>>(vg_ln_g, vg_ln_b, out_wts, out_sel);
}

// round 8
// speedup vs baseline: 2.4105x; 1.0896x over previous
#include <cuda_runtime.h>
#include <math.h>
#include <stdint.h>

// Problem constants
#define NTH   512
#define PAD   65
#define NV    16
#define ND    64
#define NH    256
#define NC    128
#define NTOK  8192
#define TT    64     // wg token tile
#define GT    128    // xt token tile
#define GTOK  64     // gemm token tile
#define BK    16     // gemm k-chunk
#define NS    4      // pipeline stages
#define SP    132    // xt smem pad

typedef unsigned long long u64;

// Scratch (device globals: allocation-free rule)
__device__ float g_ctxp[32 * NH];
__device__ float g_xT[NV * ND * NTOK];        // x transposed [v][d][n]
__device__ float g_h1[NV * NH * NTOK];        // elu(fc1) [v][c][n]
__device__ float g_res[NV * NH * NTOK];       // skip residual [v][c][n]
__device__ float g_h2[NV * NH * NTOK];        // fc2 out [v][c][n]
__device__ float g_a[NV * NH * NTOK];         // glu a-half [v][c][n]
__device__ float g_hv[NTOK * NV * NH];        // raw hv (pre-LN) [n][v][c]

__device__ __forceinline__ float elu_f(float x)  { return x > 0.f ? x : (__expf(x) - 1.f); }
__device__ __forceinline__ float sigm_f(float x) { return 1.f / (1.f + __expf(-x)); }
__device__ __forceinline__ float idf(float x)    { return x; }

// ---- packed fp32x2 helpers ----
__device__ __forceinline__ u64 pk2(float a, float b) {
    u64 r; asm("mov.b64 %0, {%1, %2};" : "=l"(r) : "f"(a), "f"(b)); return r;
}
__device__ __forceinline__ void fm2(u64& d, u64 a, u64 b) {
    asm("fma.rn.f32x2 %0, %1, %2, %0;" : "+l"(d) : "l"(a), "l"(b));
}
__device__ __forceinline__ float2 up2(u64 v) {
    float2 f; asm("mov.b64 {%0, %1}, %2;" : "=f"(f.x), "=f"(f.y) : "l"(v)); return f;
}

// ---- cp.async helpers ----
__device__ __forceinline__ void cpa16(unsigned int s, const void* g) {
    asm volatile("cp.async.cg.shared.global [%0], [%1], 16;" :: "r"(s), "l"(g));
}
#define CPA_COMMIT() asm volatile("cp.async.commit_group;" ::: "memory")
#define CPA_WAIT(n)  asm volatile("cp.async.wait_group %0;" :: "n"(n) : "memory")

// ===========================================================================
// Tiled GEMM core v3: block = 64 tokens x 256 cols, 256 threads, 2 blocks/SM.
// Thread tile: 8 tokens x 8 cols, cols as two split quads (cA..cA+3 and
// cA+128..cA+131, cA = lane*4) -> conflict-free 16B-stride w LDS.
// acc[c][tp]: c 0..3 -> cols cA+c ; c 4..7 -> cols cA+128+(c-4).
// ===========================================================================
#define GDECL \
    extern __shared__ float smem[]; \
    float* xs = smem; \
    float* ws = smem + NS * BK * GTOK; \
    const unsigned int xs_u = (unsigned int)__cvta_generic_to_shared(xs); \
    const unsigned int ws_u = (unsigned int)__cvta_generic_to_shared(ws); \
    const int tid = threadIdx.x; \
    const int t0  = (tid >> 5) * 8; \
    const int cA  = (tid & 31) * 4; \
    const int v   = blockIdx.y; \
    const int n0  = blockIdx.x * GTOK; \
    u64 acc[8][4];

#define GCOL(c) (cA + ((c) & 3) + (((c) >> 2) * 128))

#define GZERO() do { \
    _Pragma("unroll") for (int _c = 0; _c < 8; ++_c) \
    _Pragma("unroll") for (int _t = 0; _t < 4; ++_t) acc[_c][_t] = 0ull; \
} while (0)

// x: 16 rows x 64 floats = 4KB = 256 cpa16 (1/thread)
// w: 16 rows x 256 floats = 16KB = 1024 cpa16 (4/thread)
#define ISSUE(APTR, WPTR, WS_, k0, buf) do { \
    { int kr = tid >> 4, cc = tid & 15; \
      cpa16(xs_u + (((buf) * BK + kr) * GTOK + cc * 4) * 4, \
            (APTR) + (size_t)((k0) + kr) * NTOK + cc * 4); } \
    _Pragma("unroll") \
    for (int s2 = 0; s2 < 4; ++s2) { \
      int ci = tid + s2 * 256; int kr = ci >> 6, cc = ci & 63; \
      cpa16(ws_u + (((buf) * BK + kr) * NH + cc * 4) * 4, \
            (WPTR) + (size_t)((k0) + kr) * (WS_) + cc * 4); } \
} while (0)

#define GCHUNK(buf) do { \
    const float* xr = xs + (buf) * BK * GTOK + t0; \
    const float* wr = ws + (buf) * BK * NH + cA; \
    _Pragma("unroll") \
    for (int kk = 0; kk < BK; ++kk) { \
        float4 xa = *(const float4*)(xr + kk * GTOK); \
        float4 xb = *(const float4*)(xr + kk * GTOK + 4); \
        float4 wa = *(const float4*)(wr + kk * NH); \
        float4 wb = *(const float4*)(wr + kk * NH + 128); \
        u64 xp0 = pk2(xa.x, xa.y), xp1 = pk2(xa.z, xa.w); \
        u64 xp2 = pk2(xb.x, xb.y), xp3 = pk2(xb.z, xb.w); \
        u64 q; \
        q = pk2(wa.x, wa.x); fm2(acc[0][0], q, xp0); fm2(acc[0][1], q, xp1); fm2(acc[0][2], q, xp2); fm2(acc[0][3], q, xp3); \
        q = pk2(wa.y, wa.y); fm2(acc[1][0], q, xp0); fm2(acc[1][1], q, xp1); fm2(acc[1][2], q, xp2); fm2(acc[1][3], q, xp3); \
        q = pk2(wa.z, wa.z); fm2(acc[2][0], q, xp0); fm2(acc[2][1], q, xp1); fm2(acc[2][2], q, xp2); fm2(acc[2][3], q, xp3); \
        q = pk2(wa.w, wa.w); fm2(acc[3][0], q, xp0); fm2(acc[3][1], q, xp1); fm2(acc[3][2], q, xp2); fm2(acc[3][3], q, xp3); \
        q = pk2(wb.x, wb.x); fm2(acc[4][0], q, xp0); fm2(acc[4][1], q, xp1); fm2(acc[4][2], q, xp2); fm2(acc[4][3], q, xp3); \
        q = pk2(wb.y, wb.y); fm2(acc[5][0], q, xp0); fm2(acc[5][1], q, xp1); fm2(acc[5][2], q, xp2); fm2(acc[5][3], q, xp3); \
        q = pk2(wb.z, wb.z); fm2(acc[6][0], q, xp0); fm2(acc[6][1], q, xp1); fm2(acc[6][2], q, xp2); fm2(acc[6][3], q, xp3); \
        q = pk2(wb.w, wb.w); fm2(acc[7][0], q, xp0); fm2(acc[7][1], q, xp1); fm2(acc[7][2], q, xp2); fm2(acc[7][3], q, xp3); \
    } \
} while (0)

// 4-deep pipeline, one barrier per chunk.
#define GRUN(APTR, WPTR, WS_, KN) do { \
    const int nkc = (KN) / BK; \
    _Pragma("unroll") \
    for (int p = 0; p < NS - 1; ++p) { \
        if (p < nkc) { ISSUE(APTR, WPTR, WS_, p * BK, p); CPA_COMMIT(); } \
    } \
    for (int kc = 0; kc < nkc; ++kc) { \
        CPA_WAIT(NS - 2); \
        __syncthreads(); \
        if (kc + NS - 1 < nkc) { \
            ISSUE(APTR, WPTR, WS_, (kc + NS - 1) * BK, (kc + NS - 1) % NS); \
            CPA_COMMIT(); \
        } \
        GCHUNK(kc % NS); \
    } \
} while (0)

// Epilogue: bias + OP, store [c][NTOK] (tokens contiguous)
#define GEPI(OUTP, BIASP, OP) do { \
    _Pragma("unroll") \
    for (int c = 0; c < 8; ++c) { \
        int col = GCOL(c); float bb = (BIASP)[col]; \
        float2 p0 = up2(acc[c][0]), p1 = up2(acc[c][1]); \
        float2 p2 = up2(acc[c][2]), p3 = up2(acc[c][3]); \
        float* d = (OUTP) + (size_t)col * NTOK + n0 + t0; \
        *(float4*)d       = make_float4(OP(p0.x + bb), OP(p0.y + bb), OP(p1.x + bb), OP(p1.y + bb)); \
        *(float4*)(d + 4) = make_float4(OP(p2.x + bb), OP(p2.y + bb), OP(p3.x + bb), OP(p3.y + bb)); \
    } \
} while (0)

// ---------------------------------------------------------------------------
// Kernel 0: context projection
// ---------------------------------------------------------------------------
__global__ void ctx_kernel(const float* __restrict__ ctx, const float* __restrict__ wctx)
{
    int b = blockIdx.x;
    int h = threadIdx.x;
    float acc = 0.f;
    for (int c = 0; c < NC; ++c)
        acc += ctx[b * NC + c] * wctx[c * NH + h];
    g_ctxp[b * NH + h] = acc;
}

// ---------------------------------------------------------------------------
// Kernel: transpose x[n][v][d] -> g_xT[v][d][n]
// ---------------------------------------------------------------------------
__global__ void xt_kernel(const float* __restrict__ x)
{
    __shared__ float s[64 * SP];
    const int v  = blockIdx.y;
    const int n0 = blockIdx.x * GT;
    const int tid = threadIdx.x;

#pragma unroll
    for (int r = 0; r < 8; ++r) {
        int idx = tid + r * 256;
        int t  = idx >> 4;
        int dq = idx & 15;
        float4 val = *(const float4*)(x + (size_t)(n0 + t) * 1024 + v * 64 + dq * 4);
        s[(dq * 4 + 0) * SP + t] = val.x;
        s[(dq * 4 + 1) * SP + t] = val.y;
        s[(dq * 4 + 2) * SP + t] = val.z;
        s[(dq * 4 + 3) * SP + t] = val.w;
    }
    __syncthreads();
#pragma unroll
    for (int r = 0; r < 8; ++r) {
        int idx = tid + r * 256;
        int d  = idx >> 5;
        int tq = idx & 31;
        float4 o = *(const float4*)(s + d * SP + tq * 4);
        *(float4*)(g_xT + ((size_t)v * ND + d) * NTOK + n0 + tq * 4) = o;
    }
}

// ---------------------------------------------------------------------------
// Kernel 1: weight GRN -> softmax weights (unchanged)
// ---------------------------------------------------------------------------
#define GSTEP(ACC) do { \
    u64 _xp; \
    _xp = pk2(xs0, xs0); fm2(ACC[0][0], wA.x, _xp); fm2(ACC[0][1], wA.y, _xp); fm2(ACC[0][2], wB.x, _xp); fm2(ACC[0][3], wB.y, _xp); \
    _xp = pk2(xs1, xs1); fm2(ACC[1][0], wA.x, _xp); fm2(ACC[1][1], wA.y, _xp); fm2(ACC[1][2], wB.x, _xp); fm2(ACC[1][3], wB.y, _xp); \
    _xp = pk2(xs2, xs2); fm2(ACC[2][0], wA.x, _xp); fm2(ACC[2][1], wA.y, _xp); fm2(ACC[2][2], wB.x, _xp); fm2(ACC[2][3], wB.y, _xp); \
    _xp = pk2(xs3, xs3); fm2(ACC[3][0], wA.x, _xp); fm2(ACC[3][1], wA.y, _xp); fm2(ACC[3][2], wB.x, _xp); fm2(ACC[3][3], wB.y, _xp); \
} while (0)

#define ZERO44(ACC) do { \
    _Pragma("unroll") for (int _i = 0; _i < 4; ++_i) \
    _Pragma("unroll") for (int _j = 0; _j < 4; ++_j) ACC[_i][_j] = 0ull; \
} while (0)

__global__ __launch_bounds__(NTH, 1)
void wg_kernel(const float* __restrict__ x,
               const float* __restrict__ fc1w, const float* __restrict__ fc1b,
               const float* __restrict__ fc2w, const float* __restrict__ fc2b,
               const float* __restrict__ gluw, const float* __restrict__ glub,
               const float* __restrict__ skw,  const float* __restrict__ skb,
               const float* __restrict__ lng,  const float* __restrict__ lnb,
               float* __restrict__ outw)
{
    extern __shared__ float sm[];
    float* sx  = sm;                       // [128][PAD]
    float* ash = sx  + 128 * PAD;          // [256][PAD]
    float* bsh = ash + 256 * PAD;          // [256][PAD]
    float* rsh = bsh + 256 * PAD;          // [64][16]
    float* gsh = rsh + 64 * 16;            // [64][32]

    const int tid  = threadIdx.x;
    const int warp = tid >> 5, lane = tid & 31;
    const int t0 = warp * 4;
    const int c0 = lane * 8;
    const int n0 = blockIdx.x * TT;
    const int tR = tid >> 3, jR = tid & 7;

    u64 acc[4][4];
    ZERO44(acc);
    float r0 = 0.f, r1 = 0.f;

    for (int kt = 0; kt < 8; ++kt) {
        for (int i = tid; i < TT * 128; i += NTH) {
            int t = i >> 7, k = i & 127;
            sx[k * PAD + t] = x[(size_t)(n0 + t) * 1024 + kt * 128 + k];
        }
        __syncthreads();
        const float* W = fc1w + (size_t)(kt * 128) * NH + c0;
#pragma unroll 2
        for (int k = 0; k < 128; ++k) {
            ulonglong2 wA = *(const ulonglong2*)(W + (size_t)k * NH);
            ulonglong2 wB = *(const ulonglong2*)(W + (size_t)k * NH + 4);
            float xs0 = sx[k * PAD + t0 + 0];
            float xs1 = sx[k * PAD + t0 + 1];
            float xs2 = sx[k * PAD + t0 + 2];
            float xs3 = sx[k * PAD + t0 + 3];
            GSTEP(acc);
        }
        const float* Ws = skw + (size_t)(kt * 128) * NV;
#pragma unroll 4
        for (int k = 0; k < 128; ++k) {
            float xv = sx[k * PAD + tR];
            r0 += xv * Ws[k * NV + jR];
            r1 += xv * Ws[k * NV + jR + 8];
        }
        __syncthreads();
    }

    {
        const int b = n0 >> 8;
#pragma unroll
        for (int j = 0; j < 4; ++j) {
            int ca = c0 + 2 * j, cb = ca + 1;
            float ba = fc1b[ca] + g_ctxp[b * NH + ca];
            float bb = fc1b[cb] + g_ctxp[b * NH + cb];
#pragma unroll
            for (int i = 0; i < 4; ++i) {
                float2 p = up2(acc[i][j]);
                ash[ca * PAD + t0 + i] = elu_f(p.x + ba);
                ash[cb * PAD + t0 + i] = elu_f(p.y + bb);
            }
        }
        rsh[tR * 16 + jR]     = r0 + skb[jR];
        rsh[tR * 16 + jR + 8] = r1 + skb[jR + 8];
    }
    __syncthreads();

    ZERO44(acc);
    {
        const float* W2 = fc2w + c0;
#pragma unroll 2
        for (int k = 0; k < NH; ++k) {
            ulonglong2 wA = *(const ulonglong2*)(W2 + (size_t)k * NH);
            ulonglong2 wB = *(const ulonglong2*)(W2 + (size_t)k * NH + 4);
            float xs0 = ash[k * PAD + t0 + 0];
            float xs1 = ash[k * PAD + t0 + 1];
            float xs2 = ash[k * PAD + t0 + 2];
            float xs3 = ash[k * PAD + t0 + 3];
            GSTEP(acc);
        }
#pragma unroll
        for (int j = 0; j < 4; ++j) {
            int ca = c0 + 2 * j, cb = ca + 1;
            float ba = fc2b[ca], bb = fc2b[cb];
#pragma unroll
            for (int i = 0; i < 4; ++i) {
                float2 p = up2(acc[i][j]);
                bsh[ca * PAD + t0 + i] = p.x + ba;
                bsh[cb * PAD + t0 + i] = p.y + bb;
            }
        }
    }
    __syncthreads();

    {
        float a3[4] = {0.f, 0.f, 0.f, 0.f};
#pragma unroll 4
        for (int k = 0; k < NH; ++k) {
            float w = gluw[k * 32 + lane];
            a3[0] += bsh[k * PAD + t0 + 0] * w;
            a3[1] += bsh[k * PAD + t0 + 1] * w;
            a3[2] += bsh[k * PAD + t0 + 2] * w;
            a3[3] += bsh[k * PAD + t0 + 3] * w;
        }
        float gb = glub[lane];
#pragma unroll
        for (int i = 0; i < 4; ++i)
            gsh[(t0 + i) * 32 + lane] = a3[i] + gb;
    }
    __syncthreads();

    if (tid < TT) {
        int t = tid;
        float h[NV];
        float mu = 0.f;
#pragma unroll
        for (int v = 0; v < NV; ++v) {
            float a  = gsh[t * 32 + v];
            float bb = gsh[t * 32 + 16 + v];
            h[v] = a * sigm_f(bb) + rsh[t * 16 + v];
            mu += h[v];
        }
        mu *= (1.f / 16.f);
        float var = 0.f;
#pragma unroll
        for (int v = 0; v < NV; ++v) { float d = h[v] - mu; var += d * d; }
        var *= (1.f / 16.f);
        float rstd = rsqrtf(var + 1e-5f);
        float y[NV], m = -1e30f;
#pragma unroll
        for (int v = 0; v < NV; ++v) {
            y[v] = (h[v] - mu) * rstd * lng[v] + lnb[v];
            m = fmaxf(m, y[v]);
        }
        float s = 0.f;
#pragma unroll
        for (int v = 0; v < NV; ++v) { y[v] = __expf(y[v] - m); s += y[v]; }
        float inv = 1.f / s;
#pragma unroll
        for (int v = 0; v < NV; ++v)
            outw[(n0 + t) * NV + v] = y[v] * inv;
    }
}

// ---------------------------------------------------------------------------
// Kernel 2a: h1 = elu(x @ fc1 + b1), res = x @ skip + bs   (K = 64)
// ---------------------------------------------------------------------------
__global__ __launch_bounds__(256, 2)
void fc1skip_kernel(const float* __restrict__ fc1w, const float* __restrict__ fc1b,
                    const float* __restrict__ skw,  const float* __restrict__ skb)
{
    GDECL;
    const float* A  = g_xT + (size_t)v * ND * NTOK + n0;
    const float* W1 = fc1w + (size_t)v * ND * NH;
    const float* W2 = skw  + (size_t)v * ND * NH;

    GZERO();
    GRUN(A, W1, NH, ND);
    GEPI(g_h1 + (size_t)v * NH * NTOK, fc1b + v * NH, elu_f);

    GZERO();
    GRUN(A, W2, NH, ND);
    GEPI(g_res + (size_t)v * NH * NTOK, skb + v * NH, idf);
}

// ---------------------------------------------------------------------------
// Kernel 2b: h2 = h1 @ fc2 + b2   (K = 256)
// ---------------------------------------------------------------------------
__global__ __launch_bounds__(256, 2)
void fc2_kernel(const float* __restrict__ fc2w, const float* __restrict__ fc2b)
{
    GDECL;
    const float* A = g_h1 + (size_t)v * NH * NTOK + n0;
    const float* W = fc2w + (size_t)v * NH * NH;

    GZERO();
    GRUN(A, W, NH, NH);
    GEPI(g_h2 + (size_t)v * NH * NTOK, fc2b + v * NH, idf);
}

// ---------------------------------------------------------------------------
// Kernel 2c-1: a-half of GLU -> g_a   (K = 256)
// ---------------------------------------------------------------------------
__global__ __launch_bounds__(256, 2)
void glu_a_kernel(const float* __restrict__ gluw, const float* __restrict__ glub)
{
    GDECL;
    const float* A = g_h2 + (size_t)v * NH * NTOK + n0;
    const float* W = gluw + (size_t)v * NH * 512;

    GZERO();
    GRUN(A, W, 512, NH);
    GEPI(g_a + (size_t)v * NH * NTOK, glub + v * 512, idf);
}

// ---------------------------------------------------------------------------
// Kernel 2c-2: b-half + combine: hv = a * sigm(b) + res -> g_hv [n][v][c]
// ---------------------------------------------------------------------------
__global__ __launch_bounds__(256, 2)
void glu_b_kernel(const float* __restrict__ gluw, const float* __restrict__ glub)
{
    GDECL;
    const float* A = g_h2 + (size_t)v * NH * NTOK + n0;
    const float* W = gluw + (size_t)v * NH * 512 + 256;

    GZERO();
    GRUN(A, W, 512, NH);

    // combine: hv = a * sigm(b + bias) + res, repack into acc
#pragma unroll
    for (int c = 0; c < 8; ++c) {
        int col = GCOL(c);
        float bb = glub[v * 512 + 256 + col];
        const float* ap = g_a   + ((size_t)v * NH + col) * NTOK + n0 + t0;
        const float* rp = g_res + ((size_t)v * NH + col) * NTOK + n0 + t0;
        float4 a0 = *(const float4*)ap, a1 = *(const float4*)(ap + 4);
        float4 r0 = *(const float4*)rp, r1 = *(const float4*)(rp + 4);
        float2 p0 = up2(acc[c][0]), p1 = up2(acc[c][1]);
        float2 p2 = up2(acc[c][2]), p3 = up2(acc[c][3]);
        float h0 = a0.x * sigm_f(p0.x + bb) + r0.x;
        float h1 = a0.y * sigm_f(p0.y + bb) + r0.y;
        float h2 = a0.z * sigm_f(p1.x + bb) + r0.z;
        float h3 = a0.w * sigm_f(p1.y + bb) + r0.w;
        float h4 = a1.x * sigm_f(p2.x + bb) + r1.x;
        float h5 = a1.y * sigm_f(p2.y + bb) + r1.y;
        float h6 = a1.z * sigm_f(p3.x + bb) + r1.z;
        float h7 = a1.w * sigm_f(p3.y + bb) + r1.w;
        acc[c][0] = pk2(h0, h1); acc[c][1] = pk2(h2, h3);
        acc[c][2] = pk2(h4, h5); acc[c][3] = pk2(h6, h7);
    }

    // transpose store: per token, two float4 col-spans -> g_hv[n][v][c]
#pragma unroll
    for (int tp = 0; tp < 4; ++tp) {
        float2 q0 = up2(acc[0][tp]), q1 = up2(acc[1][tp]);
        float2 q2 = up2(acc[2][tp]), q3 = up2(acc[3][tp]);
        float2 q4 = up2(acc[4][tp]), q5 = up2(acc[5][tp]);
        float2 q6 = up2(acc[6][tp]), q7 = up2(acc[7][tp]);
        float* dA = g_hv + (size_t)(n0 + t0 + 2 * tp)     * (NV * NH) + v * NH;
        float* dB = g_hv + (size_t)(n0 + t0 + 2 * tp + 1) * (NV * NH) + v * NH;
        *(float4*)(dA + cA)       = make_float4(q0.x, q1.x, q2.x, q3.x);
        *(float4*)(dA + cA + 128) = make_float4(q4.x, q5.x, q6.x, q7.x);
        *(float4*)(dB + cA)       = make_float4(q0.y, q1.y, q2.y, q3.y);
        *(float4*)(dB + cA + 128) = make_float4(q4.y, q5.y, q6.y, q7.y);
    }
}

// ---------------------------------------------------------------------------
// Kernel 3: per-token LN(256) per v + weight scale + sum over v -> selected
// ---------------------------------------------------------------------------
__global__ void combine_kernel(const float* __restrict__ lng, const float* __restrict__ lnb,
                               const float* __restrict__ wts, float* __restrict__ out_sel)
{
    __shared__ float s_part[8 * 260];
    const int n = blockIdx.x;
    const int tid = threadIdx.x;
    const int w = tid >> 5, lane = tid & 31;

    float psum[8];
#pragma unroll
    for (int j = 0; j < 8; ++j) psum[j] = 0.f;

#pragma unroll
    for (int vv = 0; vv < 2; ++vv) {
        int v = w * 2 + vv;
        const float* p = g_hv + (size_t)n * (NV * NH) + v * NH + lane * 8;
        float4 u0 = *(const float4*)p, u1 = *(const float4*)(p + 4);
        float uu[8] = {u0.x, u0.y, u0.z, u0.w, u1.x, u1.y, u1.z, u1.w};
        float s = 0.f, s2 = 0.f;
#pragma unroll
        for (int j = 0; j < 8; ++j) { s += uu[j]; s2 += uu[j] * uu[j]; }
#pragma unroll
        for (int off = 16; off > 0; off >>= 1) {
            s  += __shfl_xor_sync(0xffffffffu, s,  off);
            s2 += __shfl_xor_sync(0xffffffffu, s2, off);
        }
        float mu   = s * (1.f / 256.f);
        float var  = s2 * (1.f / 256.f) - mu * mu;
        float rstd = rsqrtf(var + 1e-5f);
        float wv = wts[n * NV + v];
#pragma unroll
        for (int j = 0; j < 8; ++j) {
            int c = lane * 8 + j;
            float y = (uu[j] - mu) * rstd * lng[v * NH + c] + lnb[v * NH + c];
            psum[j] += y * wv;
        }
    }

    *(float4*)(s_part + w * 260 + lane * 8)     = make_float4(psum[0], psum[1], psum[2], psum[3]);
    *(float4*)(s_part + w * 260 + lane * 8 + 4) = make_float4(psum[4], psum[5], psum[6], psum[7]);
    __syncthreads();

    float s = 0.f;
#pragma unroll
    for (int w8 = 0; w8 < 8; ++w8) s += s_part[w8 * 260 + tid];
    out_sel[(size_t)n * NH + tid] = s;
}

// ---------------------------------------------------------------------------
extern "C" void kernel_launch(void* const* d_in, const int* in_sizes, int n_in,
                              void* d_out, int out_size)
{
    const float* x        = (const float*)d_in[0];
    const float* context  = (const float*)d_in[1];
    const float* vg_fc1_w = (const float*)d_in[2];
    const float* vg_fc1_b = (const float*)d_in[3];
    const float* vg_fc2_w = (const float*)d_in[4];
    const float* vg_fc2_b = (const float*)d_in[5];
    const float* vg_glu_w = (const float*)d_in[6];
    const float* vg_glu_b = (const float*)d_in[7];
    const float* vg_skip_w= (const float*)d_in[8];
    const float* vg_skip_b= (const float*)d_in[9];
    const float* vg_ln_g  = (const float*)d_in[10];
    const float* vg_ln_b  = (const float*)d_in[11];
    const float* wg_fc1_w = (const float*)d_in[12];
    const float* wg_fc1_b = (const float*)d_in[13];
    const float* wg_ctx_w = (const float*)d_in[14];
    const float* wg_fc2_w = (const float*)d_in[15];
    const float* wg_fc2_b = (const float*)d_in[16];
    const float* wg_glu_w = (const float*)d_in[17];
    const float* wg_glu_b = (const float*)d_in[18];
    const float* wg_skip_w= (const float*)d_in[19];
    const float* wg_skip_b= (const float*)d_in[20];
    const float* wg_ln_g  = (const float*)d_in[21];
    const float* wg_ln_b  = (const float*)d_in[22];

    float* out      = (float*)d_out;
    float* out_sel  = out;
    float* out_wts  = out + (size_t)NTOK * NH;

    const int WG_SMEM = (128 * PAD + 2 * 256 * PAD + 64 * 16 + 64 * 32) * 4;
    const int G_SMEM  = NS * BK * (GTOK + NH) * 4;   // 80KB/block
    cudaFuncSetAttribute(wg_kernel,      cudaFuncAttributeMaxDynamicSharedMemorySize, WG_SMEM);
    cudaFuncSetAttribute(fc1skip_kernel, cudaFuncAttributeMaxDynamicSharedMemorySize, G_SMEM);
    cudaFuncSetAttribute(fc2_kernel,     cudaFuncAttributeMaxDynamicSharedMemorySize, G_SMEM);
    cudaFuncSetAttribute(glu_a_kernel,   cudaFuncAttributeMaxDynamicSharedMemorySize, G_SMEM);
    cudaFuncSetAttribute(glu_b_kernel,   cudaFuncAttributeMaxDynamicSharedMemorySize, G_SMEM);

    const dim3 xgrid(NTOK / GT, NV);
    const dim3 ggrid(NTOK / GTOK, NV);

    ctx_kernel<<<32, NH>>>(context, wg_ctx_w);
    xt_kernel<<<xgrid, 256>>>(x);
    wg_kernel<<<NTOK / TT, NTH, WG_SMEM>>>(
        x, wg_fc1_w, wg_fc1_b, wg_fc2_w, wg_fc2_b,
        wg_glu_w, wg_glu_b, wg_skip_w, wg_skip_b, wg_ln_g, wg_ln_b, out_wts);

    fc1skip_kernel<<<ggrid, 256, G_SMEM>>>(vg_fc1_w, vg_fc1_b, vg_skip_w, vg_skip_b);
    fc2_kernel<<<ggrid, 256, G_SMEM>>>(vg_fc2_w, vg_fc2_b);
    glu_a_kernel<<<ggrid, 256, G_SMEM>>>(vg_glu_w, vg_glu_b);
    glu_b_kernel<<<ggrid, 256, G_SMEM>>>(vg_glu_w, vg_glu_b);

    combine_kernel<<<NTOK, 256>>>(vg_ln_g, vg_ln_b, out_wts, out_sel);
}